// round 4
// baseline (speedup 1.0000x reference)
#include <cuda_runtime.h>
#include <cuda_fp16.h>

#define HW 65536

// ---- scratch (device globals: the sanctioned no-alloc path) ----
__device__ float g_q [8 * 8  * HW];   // [B,Cq,H,W]
__device__ float g_k [8 * 8  * HW];
__device__ float g_qT[8 * 8  * HW];   // [B,Cq,W,H]
__device__ float g_kT[8 * 8  * HW];
__device__ float g_v [8 * 64 * HW];   // [B,C,H,W]
__device__ float g_vT[8 * 64 * HW];   // [B,C,W,H]
__device__ float g_hT[8 * 64 * HW];   // column-attn out, [B,C,W,H]
__device__ float g_w [8 * 64 * HW];   // row-attn out,    [B,C,H,W]

// ---- packed fp32x2 (sm_103a FFMA2) ----
__device__ __forceinline__ unsigned long long pk2(float lo, float hi) {
    unsigned long long r;
    asm("mov.b64 %0, {%1, %2};" : "=l"(r) : "f"(lo), "f"(hi));
    return r;
}
__device__ __forceinline__ float2 upk2(unsigned long long v) {
    float2 f;
    asm("mov.b64 {%0, %1}, %2;" : "=f"(f.x), "=f"(f.y) : "l"(v));
    return f;
}
__device__ __forceinline__ unsigned long long ffma2(unsigned long long a,
                                                    unsigned long long b,
                                                    unsigned long long c) {
    unsigned long long d;
    asm("fma.rn.f32x2 %0, %1, %2, %3;" : "=l"(d) : "l"(a), "l"(b), "l"(c));
    return d;
}

// ---- fast exp for x<=0 on the FMA pipe (no MUFU) ----
__device__ __forceinline__ float fexp(float x) {
    x = fmaxf(x, -80.0f);
    const float L2E = 1.4426950408889634f;
    float t = fmaf(x, L2E, 12582912.0f);
    float n = t - 12582912.0f;
    float f = fmaf(x, L2E, -n);
    float p = fmaf(f, 0.0096181291f, 0.0555041087f);
    p = fmaf(f, p, 0.2402265069f);
    p = fmaf(f, p, 0.6931471806f);
    p = fmaf(f, p, 1.0f);
    return __int_as_float(__float_as_int(p) + (__float_as_int(t) << 23));
}

// ---- K1: fused 1x1-conv projections q,k,v ----
__device__ __forceinline__ void proj_store(int o, float val, int b, int hw) {
    if (o < 8)       g_q[((b * 8  + o       ) << 16) + hw] = val;
    else if (o < 16) g_k[((b * 8  + (o - 8 )) << 16) + hw] = val;
    else             g_v[((b * 64 + (o - 16)) << 16) + hw] = val;
}

__global__ __launch_bounds__(256) void proj_kernel(
    const float* __restrict__ x,
    const float* __restrict__ Wq, const float* __restrict__ bq,
    const float* __restrict__ Wk, const float* __restrict__ bk,
    const float* __restrict__ Wv, const float* __restrict__ bv)
{
    __shared__ float ws[64][80];
    __shared__ float bs[80];
    int tid = threadIdx.x;
    for (int idx = tid; idx < 64 * 80; idx += 256) {
        int c = idx / 80, o = idx % 80;
        float wv;
        if (o < 8)       wv = Wq[o * 64 + c];
        else if (o < 16) wv = Wk[(o - 8) * 64 + c];
        else             wv = Wv[(o - 16) * 64 + c];
        ws[c][o] = wv;
    }
    if (tid < 80) bs[tid] = (tid < 8) ? bq[tid] : (tid < 16 ? bk[tid - 8] : bv[tid - 16]);
    __syncthreads();

    int p  = blockIdx.x * 256 + tid;
    int b  = p >> 16;
    int hw = p & 65535;
    const float* xp = x + ((long)(b * 64) << 16) + hw;

    unsigned long long av[40];
    #pragma unroll
    for (int o = 0; o < 40; o++) av[o] = pk2(bs[2 * o], bs[2 * o + 1]);

    #pragma unroll 4
    for (int c = 0; c < 64; c++) {
        float xv = xp[c << 16];
        unsigned long long x2 = pk2(xv, xv);
        const unsigned long long* wr = (const unsigned long long*)(&ws[c][0]);
        #pragma unroll
        for (int o = 0; o < 40; o++) av[o] = ffma2(wr[o], x2, av[o]);
    }
    #pragma unroll
    for (int o2 = 0; o2 < 40; o2++) {
        float2 f = upk2(av[o2]);
        proj_store(2 * o2,     f.x, b, hw);
        proj_store(2 * o2 + 1, f.y, b, hw);
    }
}

// ---- K1b: tiled transpose of all q,k,v planes ----
__global__ void transpose_all()
{
    __shared__ float t[32][33];
    int p = blockIdx.z;
    const float* s; float* d;
    if (p < 64)       { s = g_q + (p << 16);         d = g_qT + (p << 16); }
    else if (p < 128) { s = g_k + ((p - 64) << 16);  d = g_kT + ((p - 64) << 16); }
    else              { s = g_v + ((p - 128) << 16); d = g_vT + ((p - 128) << 16); }
    int x0 = blockIdx.x << 5, y0 = blockIdx.y << 5;
    int tx = threadIdx.x, ty = threadIdx.y;
    #pragma unroll
    for (int yy = 0; yy < 32; yy += 8)
        t[ty + yy][tx] = s[(y0 + ty + yy) * 256 + x0 + tx];
    __syncthreads();
    #pragma unroll
    for (int yy = 0; yy < 32; yy += 8)
        d[(x0 + ty + yy) * 256 + y0 + tx] = t[tx][ty + yy];
}

// ---- K2: line attention. blockIdx>>11 selects mode (0=row native, 1=col transposed)
#define ATTN_SMEM 224256
__global__ __launch_bounds__(512, 1) void attn_kernel()
{
    extern __shared__ float smem_f[];
    float*  sq    = smem_f;                     // [8][256]
    float*  sk    = smem_f + 2048;              // [8][256]
    float*  sv    = smem_f + 4096;              // [256][68] padded
    __half* sP    = (__half*)(smem_f + 21504);  // [256][264] padded
    float*  sred  = (float*)(sP + 256 * 264);   // [512]
    float*  slinv = sred + 512;                 // [256]

    int mode = blockIdx.x >> 11;
    int n    = blockIdx.x & 2047;
    const float *qb, *kb, *vb; float* ob;
    if (mode == 0) { qb = g_q;  kb = g_k;  vb = g_v;  ob = g_w;  }
    else           { qb = g_qT; kb = g_kT; vb = g_vT; ob = g_hT; }

    int tid  = threadIdx.x;
    int b    = n >> 8, line = n & 255;
    const float* q0 = qb + ((b * 8)  << 16) + (line << 8);
    const float* k0 = kb + ((b * 8)  << 16) + (line << 8);
    const float* v0 = vb + ((b * 64) << 16) + (line << 8);
    float*       o0 = ob + ((b * 64) << 16) + (line << 8);

    for (int idx = tid; idx < 2048; idx += 512) {
        int c = idx >> 8, j = idx & 255;
        sq[idx] = q0[(c << 16) + j];
        sk[idx] = k0[(c << 16) + j];
    }
    for (int idx = tid; idx < 16384; idx += 512) {
        int c = idx >> 8, pos = idx & 255;
        sv[pos * 68 + c] = v0[(c << 16) + pos];
    }
    __syncthreads();

    int i = tid & 255, half = tid >> 8;
    int j0 = half << 7;

    unsigned long long q2[8];
    #pragma unroll
    for (int c = 0; c < 8; c++) { float qv = sq[(c << 8) + i]; q2[c] = pk2(qv, qv); }

    // pass A: row max
    float m = -1e30f;
    #pragma unroll 4
    for (int j = j0; j < j0 + 128; j += 2) {
        unsigned long long s2 = 0ULL;
        #pragma unroll
        for (int c = 0; c < 8; c++)
            s2 = ffma2(q2[c], *(const unsigned long long*)(sk + (c << 8) + j), s2);
        float2 sf = upk2(s2);
        m = fmaxf(m, fmaxf(sf.x, sf.y));
    }
    sred[tid] = m;
    __syncthreads();
    float mi = fmaxf(sred[i], sred[i + 256]);
    __syncthreads();

    // pass B: P = exp(S - m) (fp16), row sums
    float l = 0.f;
    #pragma unroll 4
    for (int j = j0; j < j0 + 128; j += 2) {
        unsigned long long s2 = 0ULL;
        #pragma unroll
        for (int c = 0; c < 8; c++)
            s2 = ffma2(q2[c], *(const unsigned long long*)(sk + (c << 8) + j), s2);
        float2 sf = upk2(s2);
        float e0 = fexp(sf.x - mi);
        float e1 = fexp(sf.y - mi);
        l += e0 + e1;
        *(__half2*)(sP + i * 264 + j) = __floats2half2_rn(e0, e1);
    }
    sred[tid] = l;
    __syncthreads();
    if (tid < 256) slinv[tid] = 1.0f / (sred[tid] + sred[tid + 256]);
    __syncthreads();

    // fold 1/l_i into V rows (K-dim index i)
    for (int idx = tid; idx < 16384; idx += 512) {
        int pos = idx >> 6, c = idx & 63;
        sv[pos * 68 + c] *= slinv[pos];
    }
    __syncthreads();

    // GEMM: O[c,j] = sum_i v'[i][c] * P[i][j]; thread tile 4c x 8j
    int cb = tid & 15, jb = tid >> 4;
    int c0 = cb << 2, jg = jb << 3;
    unsigned long long acc[4][4];
    #pragma unroll
    for (int a = 0; a < 4; a++)
        #pragma unroll
        for (int t = 0; t < 4; t++) acc[a][t] = 0ULL;

    #pragma unroll 2
    for (int ii = 0; ii < 256; ii++) {
        float4 v4 = *(const float4*)(sv + ii * 68 + c0);
        uint4 pr  = *(const uint4*)(sP + ii * 264 + jg);
        const __half2* ph = (const __half2*)&pr;
        unsigned long long p2[4];
        #pragma unroll
        for (int t = 0; t < 4; t++) {
            float2 pf = __half22float2(ph[t]);
            p2[t] = pk2(pf.x, pf.y);
        }
        unsigned long long va;
        va = pk2(v4.x, v4.x);
        #pragma unroll
        for (int t = 0; t < 4; t++) acc[0][t] = ffma2(p2[t], va, acc[0][t]);
        va = pk2(v4.y, v4.y);
        #pragma unroll
        for (int t = 0; t < 4; t++) acc[1][t] = ffma2(p2[t], va, acc[1][t]);
        va = pk2(v4.z, v4.z);
        #pragma unroll
        for (int t = 0; t < 4; t++) acc[2][t] = ffma2(p2[t], va, acc[2][t]);
        va = pk2(v4.w, v4.w);
        #pragma unroll
        for (int t = 0; t < 4; t++) acc[3][t] = ffma2(p2[t], va, acc[3][t]);
    }

    #pragma unroll
    for (int a = 0; a < 4; a++) {
        float* orow = o0 + ((c0 + a) << 16) + jg;
        #pragma unroll
        for (int t = 0; t < 4; t++) {
            float2 f = upk2(acc[a][t]);
            *(float2*)(orow + 2 * t) = f;
        }
    }
}

// ---- K3: out = gamma*(h_out + w_out) + x, de-transposing g_hT on the fly ----
__global__ void combine_kernel(const float* __restrict__ x,
                               const float* __restrict__ gamma,
                               float* __restrict__ out)
{
    __shared__ float t[32][33];
    int plane = blockIdx.z;
    const float* hT = g_hT + ((long)plane << 16);
    const float* wf = g_w  + ((long)plane << 16);
    const float* xp = x    + ((long)plane << 16);
    float*       op = out  + ((long)plane << 16);
    int h0 = blockIdx.y << 5, w0 = blockIdx.x << 5;
    int tx = threadIdx.x, ty = threadIdx.y;
    float g = gamma[0];
    #pragma unroll
    for (int yy = 0; yy < 32; yy += 8)
        t[ty + yy][tx] = hT[(w0 + ty + yy) * 256 + h0 + tx];  // t[w_local][h_local]
    __syncthreads();
    #pragma unroll
    for (int yy = 0; yy < 32; yy += 8) {
        int idx = (h0 + ty + yy) * 256 + w0 + tx;
        op[idx] = fmaf(g, t[tx][ty + yy] + wf[idx], xp[idx]);
    }
}

extern "C" void kernel_launch(void* const* d_in, const int* in_sizes, int n_in,
                              void* d_out, int out_size) {
    const float* x     = (const float*)d_in[0];
    const float* Wq    = (const float*)d_in[1];
    const float* bq    = (const float*)d_in[2];
    const float* Wk    = (const float*)d_in[3];
    const float* bk    = (const float*)d_in[4];
    const float* Wv    = (const float*)d_in[5];
    const float* bv    = (const float*)d_in[6];
    const float* gamma = (const float*)d_in[7];
    float* out = (float*)d_out;

    cudaFuncSetAttribute(attn_kernel,
                         cudaFuncAttributeMaxDynamicSharedMemorySize, ATTN_SMEM);

    proj_kernel<<<2048, 256>>>(x, Wq, bq, Wk, bk, Wv, bv);
    transpose_all<<<dim3(8, 8, 640), dim3(32, 8)>>>();
    attn_kernel<<<4096, 512, ATTN_SMEM>>>();
    combine_kernel<<<dim3(8, 8, 512), dim3(32, 8)>>>(x, gamma, out);
}

// round 6
// speedup vs baseline: 1.5503x; 1.5503x over previous
#include <cuda_runtime.h>
#include <cuda_fp16.h>

#define HW 65536

// ---- scratch (device globals: the sanctioned no-alloc path) ----
__device__ float g_q [8 * 8  * HW];   // [B,Cq,H,W]
__device__ float g_k [8 * 8  * HW];
__device__ float g_qT[8 * 8  * HW];   // [B,Cq,W,H]
__device__ float g_kT[8 * 8  * HW];
__device__ float g_v [8 * 64 * HW];   // [B,C,H,W]
__device__ float g_vT[8 * 64 * HW];   // [B,C,W,H]
__device__ float g_hT[8 * 64 * HW];   // column-attn out, [B,C,W,H]
__device__ float g_w [8 * 64 * HW];   // row-attn out,    [B,C,H,W]

// ---- packed fp32x2 ----
__device__ __forceinline__ unsigned long long pk2(float lo, float hi) {
    unsigned long long r;
    asm("mov.b64 %0, {%1, %2};" : "=l"(r) : "f"(lo), "f"(hi));
    return r;
}
__device__ __forceinline__ float2 upk2(unsigned long long v) {
    float2 f;
    asm("mov.b64 {%0, %1}, %2;" : "=f"(f.x), "=f"(f.y) : "l"(v));
    return f;
}
__device__ __forceinline__ unsigned long long ffma2(unsigned long long a,
                                                    unsigned long long b,
                                                    unsigned long long c) {
    unsigned long long d;
    asm("fma.rn.f32x2 %0, %1, %2, %3;" : "=l"(d) : "l"(a), "l"(b), "l"(c));
    return d;
}

// ---- fast exp for x<=0 on the FMA pipe (no MUFU) ----
__device__ __forceinline__ float fexp(float x) {
    x = fmaxf(x, -80.0f);
    const float L2E = 1.4426950408889634f;
    float t = fmaf(x, L2E, 12582912.0f);
    float n = t - 12582912.0f;
    float f = fmaf(x, L2E, -n);
    float p = fmaf(f, 0.0096181291f, 0.0555041087f);
    p = fmaf(f, p, 0.2402265069f);
    p = fmaf(f, p, 0.6931471806f);
    p = fmaf(f, p, 1.0f);
    return __int_as_float(__float_as_int(p) + (__float_as_int(t) << 23));
}

// ---- warp MMA helpers (baseline PTX: works on plain sm_103 target) ----
__device__ __forceinline__ unsigned smem_u32(const void* p) {
    unsigned a;
    asm("{ .reg .u64 t; cvta.to.shared.u64 t, %1; cvt.u32.u64 %0, t; }"
        : "=r"(a) : "l"(p));
    return a;
}
__device__ __forceinline__ void ldsm_x4(unsigned addr, unsigned& r0, unsigned& r1,
                                        unsigned& r2, unsigned& r3) {
    asm volatile("ldmatrix.sync.aligned.m8n8.x4.shared.b16 {%0,%1,%2,%3}, [%4];"
                 : "=r"(r0), "=r"(r1), "=r"(r2), "=r"(r3) : "r"(addr));
}
__device__ __forceinline__ void mma16816(float* d, unsigned a0, unsigned a1,
                                         unsigned a2, unsigned a3,
                                         unsigned b0, unsigned b1) {
    asm volatile(
        "mma.sync.aligned.m16n8k16.row.col.f32.f16.f16.f32 "
        "{%0,%1,%2,%3},{%4,%5,%6,%7},{%8,%9},{%0,%1,%2,%3};"
        : "+f"(d[0]), "+f"(d[1]), "+f"(d[2]), "+f"(d[3])
        : "r"(a0), "r"(a1), "r"(a2), "r"(a3), "r"(b0), "r"(b1));
}

// ---- K1: fused 1x1-conv projections q,k,v ----
__device__ __forceinline__ void proj_store(int o, float val, int b, int hw) {
    if (o < 8)       g_q[((b * 8  + o       ) << 16) + hw] = val;
    else if (o < 16) g_k[((b * 8  + (o - 8 )) << 16) + hw] = val;
    else             g_v[((b * 64 + (o - 16)) << 16) + hw] = val;
}

__global__ __launch_bounds__(256) void proj_kernel(
    const float* __restrict__ x,
    const float* __restrict__ Wq, const float* __restrict__ bq,
    const float* __restrict__ Wk, const float* __restrict__ bk,
    const float* __restrict__ Wv, const float* __restrict__ bv)
{
    __shared__ float ws[64][80];
    __shared__ float bs[80];
    int tid = threadIdx.x;
    for (int idx = tid; idx < 64 * 80; idx += 256) {
        int c = idx / 80, o = idx % 80;
        float wv;
        if (o < 8)       wv = Wq[o * 64 + c];
        else if (o < 16) wv = Wk[(o - 8) * 64 + c];
        else             wv = Wv[(o - 16) * 64 + c];
        ws[c][o] = wv;
    }
    if (tid < 80) bs[tid] = (tid < 8) ? bq[tid] : (tid < 16 ? bk[tid - 8] : bv[tid - 16]);
    __syncthreads();

    int p  = blockIdx.x * 256 + tid;
    int b  = p >> 16;
    int hw = p & 65535;
    const float* xp = x + ((long)(b * 64) << 16) + hw;

    unsigned long long av[40];
    #pragma unroll
    for (int o = 0; o < 40; o++) av[o] = pk2(bs[2 * o], bs[2 * o + 1]);

    #pragma unroll 4
    for (int c = 0; c < 64; c++) {
        float xv = xp[c << 16];
        unsigned long long x2 = pk2(xv, xv);
        const unsigned long long* wr = (const unsigned long long*)(&ws[c][0]);
        #pragma unroll
        for (int o = 0; o < 40; o++) av[o] = ffma2(wr[o], x2, av[o]);
    }
    #pragma unroll
    for (int o2 = 0; o2 < 40; o2++) {
        float2 f = upk2(av[o2]);
        proj_store(2 * o2,     f.x, b, hw);
        proj_store(2 * o2 + 1, f.y, b, hw);
    }
}

// ---- K1b: tiled transpose of all q,k,v planes ----
__global__ void transpose_all()
{
    __shared__ float t[32][33];
    int p = blockIdx.z;
    const float* s; float* d;
    if (p < 64)       { s = g_q + (p << 16);         d = g_qT + (p << 16); }
    else if (p < 128) { s = g_k + ((p - 64) << 16);  d = g_kT + ((p - 64) << 16); }
    else              { s = g_v + ((p - 128) << 16); d = g_vT + ((p - 128) << 16); }
    int x0 = blockIdx.x << 5, y0 = blockIdx.y << 5;
    int tx = threadIdx.x, ty = threadIdx.y;
    #pragma unroll
    for (int yy = 0; yy < 32; yy += 8)
        t[ty + yy][tx] = s[(y0 + ty + yy) * 256 + x0 + tx];
    __syncthreads();
    #pragma unroll
    for (int yy = 0; yy < 32; yy += 8)
        d[(x0 + ty + yy) * 256 + y0 + tx] = t[tx][ty + yy];
}

// ---- K2: line attention; O-GEMM on tensor cores (mma.sync HMMA) ----
// smem layout (bytes); P^T and V use a 264-half (528B) row stride:
// 528B = 132 words, 132 mod 32 = 4 -> 8 ldmatrix rows hit disjoint bank quads.
#define OFF_Q    0            // fp32 [8][256]                      (8192)
#define OFF_K    8192         // fp32 [8][256]                      (8192)
#define OFF_PT   16384        // fp16 P^T [j=256][stride 264]       (135168)
#define OFF_V    151552       // fp16 V   [c=64][stride 264]        (33792)
#define OFF_RED  185344       // fp32 [512]                         (2048)
#define OFF_SL2  187392       // half2 [128]                        (512)
#define ATTN_SMEM 187904

__global__ __launch_bounds__(512, 1) void attn_kernel()
{
    extern __shared__ char smem[];
    float*   sq   = (float*)(smem + OFF_Q);
    float*   sk   = (float*)(smem + OFF_K);
    float*   sred = (float*)(smem + OFF_RED);
    __half2* sl2  = (__half2*)(smem + OFF_SL2);
    unsigned sbase = smem_u32(smem);

    int mode = blockIdx.x >> 11;
    int n    = blockIdx.x & 2047;
    const float *qb, *kb, *vb; float* ob;
    if (mode == 0) { qb = g_q;  kb = g_k;  vb = g_v;  ob = g_w;  }
    else           { qb = g_qT; kb = g_kT; vb = g_vT; ob = g_hT; }

    int tid  = threadIdx.x;
    int wid  = tid >> 5;
    int lane = tid & 31;
    int b    = n >> 8, line = n & 255;
    const float* q0 = qb + ((b * 8)  << 16) + (line << 8);
    const float* k0 = kb + ((b * 8)  << 16) + (line << 8);
    const float* v0 = vb + ((b * 64) << 16) + (line << 8);
    float*       o0 = ob + ((b * 64) << 16) + (line << 8);

    // loads: q,k fp32; v -> fp16 [c][i]
    for (int idx = tid; idx < 2048; idx += 512) {
        int c = idx >> 8, j = idx & 255;
        sq[idx] = q0[(c << 16) + j];
        sk[idx] = k0[(c << 16) + j];
    }
    for (int idx = tid; idx < 8192; idx += 512) {
        int c = idx >> 7, h = idx & 127;
        float2 vv = *(const float2*)(v0 + (c << 16) + (h << 1));
        *(__half2*)(smem + OFF_V + c * 528 + h * 4) = __floats2half2_rn(vv.x, vv.y);
    }
    __syncthreads();

    int i = tid & 255, half = tid >> 8;
    int j0 = half << 7;

    unsigned long long q2[8];
    #pragma unroll
    for (int c = 0; c < 8; c++) { float qv = sq[(c << 8) + i]; q2[c] = pk2(qv, qv); }

    // pass A: row max of S[i,:]
    float m = -1e30f;
    #pragma unroll 2
    for (int j = j0; j < j0 + 128; j += 4) {
        unsigned long long sa = 0ULL, sb = 0ULL;
        #pragma unroll
        for (int c = 0; c < 8; c++) {
            float4 kv = *(const float4*)(sk + (c << 8) + j);
            sa = ffma2(q2[c], pk2(kv.x, kv.y), sa);
            sb = ffma2(q2[c], pk2(kv.z, kv.w), sb);
        }
        float2 fa = upk2(sa), fb = upk2(sb);
        m = fmaxf(m, fmaxf(fmaxf(fa.x, fa.y), fmaxf(fb.x, fb.y)));
    }
    sred[tid] = m;
    __syncthreads();
    float mi = fmaxf(sred[i], sred[i + 256]);
    __syncthreads();

    // pass B: P^T[j][i] = exp(S-m_i) (fp16), row sums
    float l = 0.f;
    #pragma unroll 2
    for (int j = j0; j < j0 + 128; j += 4) {
        unsigned long long sa = 0ULL, sb = 0ULL;
        #pragma unroll
        for (int c = 0; c < 8; c++) {
            float4 kv = *(const float4*)(sk + (c << 8) + j);
            sa = ffma2(q2[c], pk2(kv.x, kv.y), sa);
            sb = ffma2(q2[c], pk2(kv.z, kv.w), sb);
        }
        float2 fa = upk2(sa), fb = upk2(sb);
        float e0 = fexp(fa.x - mi);
        float e1 = fexp(fa.y - mi);
        float e2 = fexp(fb.x - mi);
        float e3 = fexp(fb.y - mi);
        l += (e0 + e1) + (e2 + e3);
        *(__half*)(smem + OFF_PT + (j    ) * 528 + i * 2) = __float2half_rn(e0);
        *(__half*)(smem + OFF_PT + (j + 1) * 528 + i * 2) = __float2half_rn(e1);
        *(__half*)(smem + OFF_PT + (j + 2) * 528 + i * 2) = __float2half_rn(e2);
        *(__half*)(smem + OFF_PT + (j + 3) * 528 + i * 2) = __float2half_rn(e3);
    }
    sred[tid] = l;
    __syncthreads();
    if (tid < 128) {
        int i0 = tid * 2;
        float inv0 = 1.0f / (sred[i0]     + sred[i0 + 256]);
        float inv1 = 1.0f / (sred[i0 + 1] + sred[i0 + 257]);
        sl2[tid] = __floats2half2_rn(inv0, inv1);
    }
    __syncthreads();

    // fold 1/l_i into V's i columns (K-dim)
    for (int idx = tid; idx < 8192; idx += 512) {
        int c = idx >> 7, h = idx & 127;
        __half2* vp = (__half2*)(smem + OFF_V + c * 528 + h * 4);
        *vp = __hmul2(*vp, sl2[h]);
    }
    __syncthreads();

    // tensor-core GEMM: O[c][j] = sum_i V'[c][i] * P^T[j][i]
    // A = V' row-major [m=c][k=i]; B = P^T "col-major" ([n=j][k=i] rows).
    // warp tile: 16 c x 64 j; warps: mc = wid&3, jc = wid>>2.
    {
        int mc = wid & 3, jc = wid >> 2;
        unsigned arow  = (unsigned)(mc * 16 + (lane & 7) + ((lane >> 3) & 1) * 8);
        unsigned aaddr = sbase + OFF_V + arow * 528u + (unsigned)(lane >> 4) * 16u;
        unsigned brow  = (unsigned)((lane & 7) + ((lane >> 4) ? 8 : 0));
        unsigned baddr = sbase + OFF_PT + (unsigned)(jc * 64) * 528u + brow * 528u
                       + (unsigned)((lane >> 3) & 1) * 16u;

        float acc[8][4];
        #pragma unroll
        for (int nt = 0; nt < 8; nt++)
            #pragma unroll
            for (int t = 0; t < 4; t++) acc[nt][t] = 0.f;

        #pragma unroll
        for (int kk = 0; kk < 16; kk++) {
            unsigned a0, a1, a2, a3;
            ldsm_x4(aaddr + (unsigned)kk * 32u, a0, a1, a2, a3);
            #pragma unroll
            for (int g = 0; g < 4; g++) {
                unsigned b0, b1, b2, b3;
                ldsm_x4(baddr + (unsigned)g * (16u * 528u) + (unsigned)kk * 32u,
                        b0, b1, b2, b3);
                mma16816(acc[2 * g],     a0, a1, a2, a3, b0, b1);
                mma16816(acc[2 * g + 1], a0, a1, a2, a3, b2, b3);
            }
        }

        int crow = mc * 16 + (lane >> 2);
        int jb2  = jc * 64 + (lane & 3) * 2;
        #pragma unroll
        for (int nt = 0; nt < 8; nt++) {
            int j = jb2 + nt * 8;
            *(float2*)(o0 + (crow << 16) + j)       = make_float2(acc[nt][0], acc[nt][1]);
            *(float2*)(o0 + ((crow + 8) << 16) + j) = make_float2(acc[nt][2], acc[nt][3]);
        }
    }
}

// ---- K3: out = gamma*(h_out + w_out) + x, de-transposing g_hT on the fly ----
__global__ void combine_kernel(const float* __restrict__ x,
                               const float* __restrict__ gamma,
                               float* __restrict__ out)
{
    __shared__ float t[32][33];
    int plane = blockIdx.z;
    const float* hT = g_hT + ((long)plane << 16);
    const float* wf = g_w  + ((long)plane << 16);
    const float* xp = x    + ((long)plane << 16);
    float*       op = out  + ((long)plane << 16);
    int h0 = blockIdx.y << 5, w0 = blockIdx.x << 5;
    int tx = threadIdx.x, ty = threadIdx.y;
    float g = gamma[0];
    #pragma unroll
    for (int yy = 0; yy < 32; yy += 8)
        t[ty + yy][tx] = hT[(w0 + ty + yy) * 256 + h0 + tx];
    __syncthreads();
    #pragma unroll
    for (int yy = 0; yy < 32; yy += 8) {
        int idx = (h0 + ty + yy) * 256 + w0 + tx;
        op[idx] = fmaf(g, t[tx][ty + yy] + wf[idx], xp[idx]);
    }
}

extern "C" void kernel_launch(void* const* d_in, const int* in_sizes, int n_in,
                              void* d_out, int out_size) {
    const float* x     = (const float*)d_in[0];
    const float* Wq    = (const float*)d_in[1];
    const float* bq    = (const float*)d_in[2];
    const float* Wk    = (const float*)d_in[3];
    const float* bk    = (const float*)d_in[4];
    const float* Wv    = (const float*)d_in[5];
    const float* bv    = (const float*)d_in[6];
    const float* gamma = (const float*)d_in[7];
    float* out = (float*)d_out;

    cudaFuncSetAttribute(attn_kernel,
                         cudaFuncAttributeMaxDynamicSharedMemorySize, ATTN_SMEM);

    proj_kernel<<<2048, 256>>>(x, Wq, bq, Wk, bk, Wv, bv);
    transpose_all<<<dim3(8, 8, 640), dim3(32, 8)>>>();
    attn_kernel<<<4096, 512, ATTN_SMEM>>>();
    combine_kernel<<<dim3(8, 8, 512), dim3(32, 8)>>>(x, gamma, out);
}

// round 7
// speedup vs baseline: 1.8597x; 1.1995x over previous
#include <cuda_runtime.h>
#include <cuda_fp16.h>

#define HW 65536

// ---- scratch (device globals: the sanctioned no-alloc path) ----
__device__ float g_q [8 * 8  * HW];   // [B,Cq,H,W]
__device__ float g_k [8 * 8  * HW];
__device__ float g_qT[8 * 8  * HW];   // [B,Cq,W,H]
__device__ float g_kT[8 * 8  * HW];
__device__ float g_v [8 * 64 * HW];   // [B,C,H,W]
__device__ float g_vT[8 * 64 * HW];   // [B,C,W,H]
__device__ float g_hT[8 * 64 * HW];   // column-attn out, [B,C,W,H]
__device__ float g_w [8 * 64 * HW];   // row-attn out,    [B,C,H,W]

// ---- packed fp32x2 ----
__device__ __forceinline__ unsigned long long pk2(float lo, float hi) {
    unsigned long long r;
    asm("mov.b64 %0, {%1, %2};" : "=l"(r) : "f"(lo), "f"(hi));
    return r;
}
__device__ __forceinline__ float2 upk2(unsigned long long v) {
    float2 f;
    asm("mov.b64 {%0, %1}, %2;" : "=f"(f.x), "=f"(f.y) : "l"(v));
    return f;
}
__device__ __forceinline__ unsigned long long ffma2(unsigned long long a,
                                                    unsigned long long b,
                                                    unsigned long long c) {
    unsigned long long d;
    asm("fma.rn.f32x2 %0, %1, %2, %3;" : "=l"(d) : "l"(a), "l"(b), "l"(c));
    return d;
}

// ---- fast exp for x<=0 on the FMA pipe (no MUFU) ----
__device__ __forceinline__ float fexp(float x) {
    x = fmaxf(x, -80.0f);
    const float L2E = 1.4426950408889634f;
    float t = fmaf(x, L2E, 12582912.0f);
    float n = t - 12582912.0f;
    float f = fmaf(x, L2E, -n);
    float p = fmaf(f, 0.0096181291f, 0.0555041087f);
    p = fmaf(f, p, 0.2402265069f);
    p = fmaf(f, p, 0.6931471806f);
    p = fmaf(f, p, 1.0f);
    return __int_as_float(__float_as_int(p) + (__float_as_int(t) << 23));
}

// ---- warp MMA helpers (baseline PTX: works on plain sm_103 target) ----
__device__ __forceinline__ unsigned smem_u32(const void* p) {
    unsigned a;
    asm("{ .reg .u64 t; cvta.to.shared.u64 t, %1; cvt.u32.u64 %0, t; }"
        : "=r"(a) : "l"(p));
    return a;
}
__device__ __forceinline__ void ldsm_x4(unsigned addr, unsigned& r0, unsigned& r1,
                                        unsigned& r2, unsigned& r3) {
    asm volatile("ldmatrix.sync.aligned.m8n8.x4.shared.b16 {%0,%1,%2,%3}, [%4];"
                 : "=r"(r0), "=r"(r1), "=r"(r2), "=r"(r3) : "r"(addr));
}
__device__ __forceinline__ void mma16816(float* d, unsigned a0, unsigned a1,
                                         unsigned a2, unsigned a3,
                                         unsigned b0, unsigned b1) {
    asm volatile(
        "mma.sync.aligned.m16n8k16.row.col.f32.f16.f16.f32 "
        "{%0,%1,%2,%3},{%4,%5,%6,%7},{%8,%9},{%0,%1,%2,%3};"
        : "+f"(d[0]), "+f"(d[1]), "+f"(d[2]), "+f"(d[3])
        : "r"(a0), "r"(a1), "r"(a2), "r"(a3), "r"(b0), "r"(b1));
}

// ---- K1: fused 1x1-conv projections q,k,v ----
__device__ __forceinline__ void proj_store(int o, float val, int b, int hw) {
    if (o < 8)       g_q[((b * 8  + o       ) << 16) + hw] = val;
    else if (o < 16) g_k[((b * 8  + (o - 8 )) << 16) + hw] = val;
    else             g_v[((b * 64 + (o - 16)) << 16) + hw] = val;
}

__global__ __launch_bounds__(256) void proj_kernel(
    const float* __restrict__ x,
    const float* __restrict__ Wq, const float* __restrict__ bq,
    const float* __restrict__ Wk, const float* __restrict__ bk,
    const float* __restrict__ Wv, const float* __restrict__ bv)
{
    __shared__ float ws[64][80];
    __shared__ float bs[80];
    int tid = threadIdx.x;
    for (int idx = tid; idx < 64 * 80; idx += 256) {
        int c = idx / 80, o = idx % 80;
        float wv;
        if (o < 8)       wv = Wq[o * 64 + c];
        else if (o < 16) wv = Wk[(o - 8) * 64 + c];
        else             wv = Wv[(o - 16) * 64 + c];
        ws[c][o] = wv;
    }
    if (tid < 80) bs[tid] = (tid < 8) ? bq[tid] : (tid < 16 ? bk[tid - 8] : bv[tid - 16]);
    __syncthreads();

    int p  = blockIdx.x * 256 + tid;
    int b  = p >> 16;
    int hw = p & 65535;
    const float* xp = x + ((long)(b * 64) << 16) + hw;

    unsigned long long av[40];
    #pragma unroll
    for (int o = 0; o < 40; o++) av[o] = pk2(bs[2 * o], bs[2 * o + 1]);

    #pragma unroll 4
    for (int c = 0; c < 64; c++) {
        float xv = xp[c << 16];
        unsigned long long x2 = pk2(xv, xv);
        const unsigned long long* wr = (const unsigned long long*)(&ws[c][0]);
        #pragma unroll
        for (int o = 0; o < 40; o++) av[o] = ffma2(wr[o], x2, av[o]);
    }
    #pragma unroll
    for (int o2 = 0; o2 < 40; o2++) {
        float2 f = upk2(av[o2]);
        proj_store(2 * o2,     f.x, b, hw);
        proj_store(2 * o2 + 1, f.y, b, hw);
    }
}

// ---- K1b: tiled transpose of all q,k,v planes ----
__global__ void transpose_all()
{
    __shared__ float t[32][33];
    int p = blockIdx.z;
    const float* s; float* d;
    if (p < 64)       { s = g_q + (p << 16);         d = g_qT + (p << 16); }
    else if (p < 128) { s = g_k + ((p - 64) << 16);  d = g_kT + ((p - 64) << 16); }
    else              { s = g_v + ((p - 128) << 16); d = g_vT + ((p - 128) << 16); }
    int x0 = blockIdx.x << 5, y0 = blockIdx.y << 5;
    int tx = threadIdx.x, ty = threadIdx.y;
    #pragma unroll
    for (int yy = 0; yy < 32; yy += 8)
        t[ty + yy][tx] = s[(y0 + ty + yy) * 256 + x0 + tx];
    __syncthreads();
    #pragma unroll
    for (int yy = 0; yy < 32; yy += 8)
        d[(x0 + ty + yy) * 256 + y0 + tx] = t[tx][ty + yy];
}

// ---- K2: line attention; i-chunked P^T for 2 CTAs/SM; HMMA O-GEMM ----
// smem layout (bytes), total 114176 -> 2 CTAs/SM:
#define OFF_K    0        // fp32 [8][256]                        (8192)
#define OFF_V    8192     // fp16 V [c=64][stride 264 halfs]      (33792)
#define OFF_PT   41984    // fp16 P^T [j=256][stride 136 halfs]   (69632)
                          //   (reused after GEMM as fp32 O staging [64][stride 264])
#define OFF_RED  111616   // fp32 [512]                           (2048)
#define OFF_SL   113664   // fp32 [128]                           (512)
#define ATTN_SMEM 114176

__global__ __launch_bounds__(512, 2) void attn_kernel()
{
    extern __shared__ char smem[];
    float* sk   = (float*)(smem + OFF_K);
    float* sred = (float*)(smem + OFF_RED);
    float* sl   = (float*)(smem + OFF_SL);
    unsigned sbase = smem_u32(smem);

    int mode = blockIdx.x >> 11;
    int n    = blockIdx.x & 2047;
    const float *qb, *kb, *vb; float* ob;
    if (mode == 0) { qb = g_q;  kb = g_k;  vb = g_v;  ob = g_w;  }
    else           { qb = g_qT; kb = g_kT; vb = g_vT; ob = g_hT; }

    int tid  = threadIdx.x;
    int wid  = tid >> 5;
    int lane = tid & 31;
    int b    = n >> 8, line = n & 255;
    const float* q0 = qb + ((b * 8)  << 16) + (line << 8);
    const float* k0 = kb + ((b * 8)  << 16) + (line << 8);
    const float* v0 = vb + ((b * 64) << 16) + (line << 8);
    float*       o0 = ob + ((b * 64) << 16) + (line << 8);

    // load K (fp32) and V (fp16, [c][i] stride 264 halfs)
    for (int idx = tid; idx < 2048; idx += 512) {
        int c = idx >> 8, j = idx & 255;
        sk[idx] = k0[(c << 16) + j];
    }
    for (int idx = tid; idx < 8192; idx += 512) {
        int c = idx >> 7, h = idx & 127;
        float2 vv = *(const float2*)(v0 + (c << 16) + (h << 1));
        *(__half2*)(smem + OFF_V + c * 528 + h * 4) = __floats2half2_rn(vv.x, vv.y);
    }
    __syncthreads();

    int il = tid & 127;            // i within chunk
    int quarter = tid >> 7;        // which 64-j slice
    int j0 = quarter << 6;

    // GEMM warp tiling (fixed across chunks)
    int mc = wid & 3, jc = wid >> 2;
    unsigned arow  = (unsigned)(mc * 16 + (lane & 7) + ((lane >> 3) & 1) * 8);
    unsigned abase = sbase + OFF_V + arow * 528u + (unsigned)(lane >> 4) * 16u;
    unsigned brow  = (unsigned)((lane & 7) + ((lane >> 4) ? 8 : 0));
    unsigned bbase = sbase + OFF_PT + ((unsigned)(jc * 64) + brow) * 272u
                   + (unsigned)((lane >> 3) & 1) * 16u;

    float acc[8][4];
    #pragma unroll
    for (int nt = 0; nt < 8; nt++)
        #pragma unroll
        for (int t = 0; t < 4; t++) acc[nt][t] = 0.f;

    for (int chunk = 0; chunk < 2; chunk++) {
        int i = (chunk << 7) + il;

        unsigned long long q2[8];
        #pragma unroll
        for (int c = 0; c < 8; c++) {
            float qv = q0[(c << 16) + i];   // coalesced per warp
            q2[c] = pk2(qv, qv);
        }

        // pass A: partial max over this thread's 64 j's
        float m = -1e30f;
        #pragma unroll 2
        for (int j = j0; j < j0 + 64; j += 4) {
            unsigned long long sa = 0ULL, sb = 0ULL;
            #pragma unroll
            for (int c = 0; c < 8; c++) {
                float4 kv = *(const float4*)(sk + (c << 8) + j);
                sa = ffma2(q2[c], pk2(kv.x, kv.y), sa);
                sb = ffma2(q2[c], pk2(kv.z, kv.w), sb);
            }
            float2 fa = upk2(sa), fb = upk2(sb);
            m = fmaxf(m, fmaxf(fmaxf(fa.x, fa.y), fmaxf(fb.x, fb.y)));
        }
        sred[tid] = m;
        __syncthreads();
        float mi = fmaxf(fmaxf(sred[il], sred[il + 128]),
                         fmaxf(sred[il + 256], sred[il + 384]));
        __syncthreads();

        // pass B: P^T[j][il] = exp(S - mi) (fp16), partial sums
        float l = 0.f;
        #pragma unroll 2
        for (int j = j0; j < j0 + 64; j += 4) {
            unsigned long long sa = 0ULL, sb = 0ULL;
            #pragma unroll
            for (int c = 0; c < 8; c++) {
                float4 kv = *(const float4*)(sk + (c << 8) + j);
                sa = ffma2(q2[c], pk2(kv.x, kv.y), sa);
                sb = ffma2(q2[c], pk2(kv.z, kv.w), sb);
            }
            float2 fa = upk2(sa), fb = upk2(sb);
            float e0 = fexp(fa.x - mi);
            float e1 = fexp(fa.y - mi);
            float e2 = fexp(fb.x - mi);
            float e3 = fexp(fb.y - mi);
            l += (e0 + e1) + (e2 + e3);
            *(__half*)(smem + OFF_PT + (j    ) * 272 + il * 2) = __float2half_rn(e0);
            *(__half*)(smem + OFF_PT + (j + 1) * 272 + il * 2) = __float2half_rn(e1);
            *(__half*)(smem + OFF_PT + (j + 2) * 272 + il * 2) = __float2half_rn(e2);
            *(__half*)(smem + OFF_PT + (j + 3) * 272 + il * 2) = __float2half_rn(e3);
        }
        sred[tid] = l;
        __syncthreads();
        if (tid < 128)
            sl[tid] = 1.0f / (((sred[tid] + sred[tid + 128]) +
                               (sred[tid + 256] + sred[tid + 384])));
        __syncthreads();

        // fold 1/l_i into V's chunk columns
        for (int idx = tid; idx < 4096; idx += 512) {
            int c = idx >> 6, hp = idx & 63;
            int i0 = hp << 1;
            __half2* vp = (__half2*)(smem + OFF_V + c * 528 + chunk * 256 + hp * 4);
            *vp = __hmul2(*vp, __floats2half2_rn(sl[i0], sl[i0 + 1]));
        }
        __syncthreads();

        // GEMM K-chunk: acc += V'[c][k] * P^T[j][k], k = 128 (8 mma k-steps)
        {
            unsigned aaddr = abase + (unsigned)chunk * 256u;
            #pragma unroll
            for (int kk = 0; kk < 8; kk++) {
                unsigned a0, a1, a2, a3;
                ldsm_x4(aaddr + (unsigned)kk * 32u, a0, a1, a2, a3);
                #pragma unroll
                for (int g = 0; g < 4; g++) {
                    unsigned b0, b1, b2, b3;
                    ldsm_x4(bbase + (unsigned)g * (16u * 272u) + (unsigned)kk * 32u,
                            b0, b1, b2, b3);
                    mma16816(acc[2 * g],     a0, a1, a2, a3, b0, b1);
                    mma16816(acc[2 * g + 1], a0, a1, a2, a3, b2, b3);
                }
            }
        }
        __syncthreads();   // protect PT before next chunk's pass B / O staging
    }

    // stage O in smem (reuse PT region as fp32 [c][j], stride 264 floats)
    {
        float* so = (float*)(smem + OFF_PT);
        int crow = mc * 16 + (lane >> 2);
        int jb2  = jc * 64 + (lane & 3) * 2;
        #pragma unroll
        for (int nt = 0; nt < 8; nt++) {
            int j = jb2 + nt * 8;
            *(float2*)(so + crow * 264 + j)       = make_float2(acc[nt][0], acc[nt][1]);
            *(float2*)(so + (crow + 8) * 264 + j) = make_float2(acc[nt][2], acc[nt][3]);
        }
        __syncthreads();
        // coalesced global store
        for (int idx = tid; idx < 4096; idx += 512) {
            int c  = idx >> 6;
            int j4 = (idx & 63) << 2;
            float4 val = *(const float4*)(so + c * 264 + j4);
            *(float4*)(o0 + (c << 16) + j4) = val;
        }
    }
}

// ---- K3: out = gamma*(h_out + w_out) + x, de-transposing g_hT on the fly ----
__global__ void combine_kernel(const float* __restrict__ x,
                               const float* __restrict__ gamma,
                               float* __restrict__ out)
{
    __shared__ float t[32][33];
    int plane = blockIdx.z;
    const float* hT = g_hT + ((long)plane << 16);
    const float* wf = g_w  + ((long)plane << 16);
    const float* xp = x    + ((long)plane << 16);
    float*       op = out  + ((long)plane << 16);
    int h0 = blockIdx.y << 5, w0 = blockIdx.x << 5;
    int tx = threadIdx.x, ty = threadIdx.y;
    float g = gamma[0];
    #pragma unroll
    for (int yy = 0; yy < 32; yy += 8)
        t[ty + yy][tx] = hT[(w0 + ty + yy) * 256 + h0 + tx];
    __syncthreads();
    #pragma unroll
    for (int yy = 0; yy < 32; yy += 8) {
        int idx = (h0 + ty + yy) * 256 + w0 + tx;
        op[idx] = fmaf(g, t[tx][ty + yy] + wf[idx], xp[idx]);
    }
}

extern "C" void kernel_launch(void* const* d_in, const int* in_sizes, int n_in,
                              void* d_out, int out_size) {
    const float* x     = (const float*)d_in[0];
    const float* Wq    = (const float*)d_in[1];
    const float* bq    = (const float*)d_in[2];
    const float* Wk    = (const float*)d_in[3];
    const float* bk    = (const float*)d_in[4];
    const float* Wv    = (const float*)d_in[5];
    const float* bv    = (const float*)d_in[6];
    const float* gamma = (const float*)d_in[7];
    float* out = (float*)d_out;

    cudaFuncSetAttribute(attn_kernel,
                         cudaFuncAttributeMaxDynamicSharedMemorySize, ATTN_SMEM);

    proj_kernel<<<2048, 256>>>(x, Wq, bq, Wk, bk, Wv, bv);
    transpose_all<<<dim3(8, 8, 640), dim3(32, 8)>>>();
    attn_kernel<<<4096, 512, ATTN_SMEM>>>();
    combine_kernel<<<dim3(8, 8, 512), dim3(32, 8)>>>(x, gamma, out);
}

// round 8
// speedup vs baseline: 2.2496x; 1.2097x over previous
#include <cuda_runtime.h>
#include <cuda_fp16.h>

#define HW 65536

// ---- scratch (device globals: the sanctioned no-alloc path) ----
__device__ float g_q [8 * 8  * HW];   // [B,Cq,H,W]
__device__ float g_k [8 * 8  * HW];
__device__ float g_qT[8 * 8  * HW];   // [B,Cq,W,H]
__device__ float g_kT[8 * 8  * HW];
__device__ float g_v [8 * 64 * HW];   // [B,C,H,W]
__device__ float g_vT[8 * 64 * HW];   // [B,C,W,H]
__device__ float g_hT[8 * 64 * HW];   // column-attn out, [B,C,W,H]
__device__ float g_w [8 * 64 * HW];   // row-attn out,    [B,C,H,W]

// ---- packed fp32x2 (used by proj) ----
__device__ __forceinline__ unsigned long long pk2(float lo, float hi) {
    unsigned long long r;
    asm("mov.b64 %0, {%1, %2};" : "=l"(r) : "f"(lo), "f"(hi));
    return r;
}
__device__ __forceinline__ float2 upk2(unsigned long long v) {
    float2 f;
    asm("mov.b64 {%0, %1}, %2;" : "=f"(f.x), "=f"(f.y) : "l"(v));
    return f;
}
__device__ __forceinline__ unsigned long long ffma2(unsigned long long a,
                                                    unsigned long long b,
                                                    unsigned long long c) {
    unsigned long long d;
    asm("fma.rn.f32x2 %0, %1, %2, %3;" : "=l"(d) : "l"(a), "l"(b), "l"(c));
    return d;
}

// ---- fast exp for bounded x on the FMA pipe (no MUFU) ----
__device__ __forceinline__ float fexp(float x) {
    x = fmaxf(x, -80.0f);
    const float L2E = 1.4426950408889634f;
    float t = fmaf(x, L2E, 12582912.0f);
    float n = t - 12582912.0f;
    float f = fmaf(x, L2E, -n);
    float p = fmaf(f, 0.0096181291f, 0.0555041087f);
    p = fmaf(f, p, 0.2402265069f);
    p = fmaf(f, p, 0.6931471806f);
    p = fmaf(f, p, 1.0f);
    return __int_as_float(__float_as_int(p) + (__float_as_int(t) << 23));
}

// ---- warp MMA helpers (baseline PTX: valid on plain sm_103 target) ----
__device__ __forceinline__ unsigned smem_u32(const void* p) {
    unsigned a;
    asm("{ .reg .u64 t; cvta.to.shared.u64 t, %1; cvt.u32.u64 %0, t; }"
        : "=r"(a) : "l"(p));
    return a;
}
__device__ __forceinline__ void ldsm_x4(unsigned addr, unsigned& r0, unsigned& r1,
                                        unsigned& r2, unsigned& r3) {
    asm volatile("ldmatrix.sync.aligned.m8n8.x4.shared.b16 {%0,%1,%2,%3}, [%4];"
                 : "=r"(r0), "=r"(r1), "=r"(r2), "=r"(r3) : "r"(addr));
}
__device__ __forceinline__ void ldsm_x2(unsigned addr, unsigned& r0, unsigned& r1) {
    asm volatile("ldmatrix.sync.aligned.m8n8.x2.shared.b16 {%0,%1}, [%2];"
                 : "=r"(r0), "=r"(r1) : "r"(addr));
}
__device__ __forceinline__ void ldsm_x1(unsigned addr, unsigned& r0) {
    asm volatile("ldmatrix.sync.aligned.m8n8.x1.shared.b16 {%0}, [%1];"
                 : "=r"(r0) : "r"(addr));
}
__device__ __forceinline__ void mma16816(float* d, unsigned a0, unsigned a1,
                                         unsigned a2, unsigned a3,
                                         unsigned b0, unsigned b1) {
    asm volatile(
        "mma.sync.aligned.m16n8k16.row.col.f32.f16.f16.f32 "
        "{%0,%1,%2,%3},{%4,%5,%6,%7},{%8,%9},{%0,%1,%2,%3};"
        : "+f"(d[0]), "+f"(d[1]), "+f"(d[2]), "+f"(d[3])
        : "r"(a0), "r"(a1), "r"(a2), "r"(a3), "r"(b0), "r"(b1));
}
__device__ __forceinline__ void mma16808(float& d0, float& d1, float& d2, float& d3,
                                         unsigned a0, unsigned a1, unsigned b0) {
    asm volatile(
        "mma.sync.aligned.m16n8k8.row.col.f32.f16.f16.f32 "
        "{%0,%1,%2,%3},{%4,%5},{%6},{%7,%8,%9,%10};"
        : "=f"(d0), "=f"(d1), "=f"(d2), "=f"(d3)
        : "r"(a0), "r"(a1), "r"(b0),
          "f"(0.f), "f"(0.f), "f"(0.f), "f"(0.f));
}

// ---- K1: fused 1x1-conv projections q,k,v ----
__device__ __forceinline__ void proj_store(int o, float val, int b, int hw) {
    if (o < 8)       g_q[((b * 8  + o       ) << 16) + hw] = val;
    else if (o < 16) g_k[((b * 8  + (o - 8 )) << 16) + hw] = val;
    else             g_v[((b * 64 + (o - 16)) << 16) + hw] = val;
}

__global__ __launch_bounds__(256) void proj_kernel(
    const float* __restrict__ x,
    const float* __restrict__ Wq, const float* __restrict__ bq,
    const float* __restrict__ Wk, const float* __restrict__ bk,
    const float* __restrict__ Wv, const float* __restrict__ bv)
{
    __shared__ float ws[64][80];
    __shared__ float bs[80];
    int tid = threadIdx.x;
    for (int idx = tid; idx < 64 * 80; idx += 256) {
        int c = idx / 80, o = idx % 80;
        float wv;
        if (o < 8)       wv = Wq[o * 64 + c];
        else if (o < 16) wv = Wk[(o - 8) * 64 + c];
        else             wv = Wv[(o - 16) * 64 + c];
        ws[c][o] = wv;
    }
    if (tid < 80) bs[tid] = (tid < 8) ? bq[tid] : (tid < 16 ? bk[tid - 8] : bv[tid - 16]);
    __syncthreads();

    int p  = blockIdx.x * 256 + tid;
    int b  = p >> 16;
    int hw = p & 65535;
    const float* xp = x + ((long)(b * 64) << 16) + hw;

    unsigned long long av[40];
    #pragma unroll
    for (int o = 0; o < 40; o++) av[o] = pk2(bs[2 * o], bs[2 * o + 1]);

    #pragma unroll 4
    for (int c = 0; c < 64; c++) {
        float xv = xp[c << 16];
        unsigned long long x2 = pk2(xv, xv);
        const unsigned long long* wr = (const unsigned long long*)(&ws[c][0]);
        #pragma unroll
        for (int o = 0; o < 40; o++) av[o] = ffma2(wr[o], x2, av[o]);
    }
    #pragma unroll
    for (int o2 = 0; o2 < 40; o2++) {
        float2 f = upk2(av[o2]);
        proj_store(2 * o2,     f.x, b, hw);
        proj_store(2 * o2 + 1, f.y, b, hw);
    }
}

// ---- K1b: tiled transpose of all q,k,v planes ----
__global__ void transpose_all()
{
    __shared__ float t[32][33];
    int p = blockIdx.z;
    const float* s; float* d;
    if (p < 64)       { s = g_q + (p << 16);         d = g_qT + (p << 16); }
    else if (p < 128) { s = g_k + ((p - 64) << 16);  d = g_kT + ((p - 64) << 16); }
    else              { s = g_v + ((p - 128) << 16); d = g_vT + ((p - 128) << 16); }
    int x0 = blockIdx.x << 5, y0 = blockIdx.y << 5;
    int tx = threadIdx.x, ty = threadIdx.y;
    #pragma unroll
    for (int yy = 0; yy < 32; yy += 8)
        t[ty + yy][tx] = s[(y0 + ty + yy) * 256 + x0 + tx];
    __syncthreads();
    #pragma unroll
    for (int yy = 0; yy < 32; yy += 8)
        d[(x0 + ty + yy) * 256 + y0 + tx] = t[tx][ty + yy];
}

// ---- K2: line attention; QK AND O both on tensor cores ----
// smem (bytes), total 114688 -> 2 CTAs/SM:
#define OFF_KT   0        // fp16 kT [j=256][c=8], 16B rows          (4096)
#define OFF_QTC  4096     // fp16 qT chunk [i=128][c=8], 16B rows    (2048)
#define OFF_V    6144     // fp16 V [c=64][stride 264 halfs]         (33792)
#define OFF_PT   39936    // fp16 P^T [j=256][stride 272B]           (69632)
                          //   (also: qT-full borrow in max phase; fp32 O staging)
#define OFF_PB   109568   // fp16 l-partials [16][128]               (4096)
#define OFF_SMAX 113664   // fp16 [256]                              (512)
#define OFF_SL   114176   // fp32 [128]                              (512)
#define ATTN_SMEM 114688

__global__ __launch_bounds__(512, 2) void attn_kernel()
{
    extern __shared__ char smem[];
    unsigned sbase = smem_u32(smem);

    int mode = blockIdx.x >> 11;
    int n    = blockIdx.x & 2047;
    const float *qb, *kb, *vb; float* ob;
    if (mode == 0) { qb = g_q;  kb = g_k;  vb = g_v;  ob = g_w;  }
    else           { qb = g_qT; kb = g_kT; vb = g_vT; ob = g_hT; }

    int tid  = threadIdx.x;
    int wid  = tid >> 5;
    int lane = tid & 31;
    int b    = n >> 8, line = n & 255;
    const float* q0 = qb + ((b * 8)  << 16) + (line << 8);
    const float* k0 = kb + ((b * 8)  << 16) + (line << 8);
    const float* v0 = vb + ((b * 64) << 16) + (line << 8);
    float*       o0 = ob + ((b * 64) << 16) + (line << 8);

    // ---- loads: kT (tid<256), qT-full into PT borrow (tid>=256), V (all) ----
    if (tid < 256) {
        int j = tid;
        __half2 h01 = __floats2half2_rn(k0[(0 << 16) + j], k0[(1 << 16) + j]);
        __half2 h23 = __floats2half2_rn(k0[(2 << 16) + j], k0[(3 << 16) + j]);
        __half2 h45 = __floats2half2_rn(k0[(4 << 16) + j], k0[(5 << 16) + j]);
        __half2 h67 = __floats2half2_rn(k0[(6 << 16) + j], k0[(7 << 16) + j]);
        uint4 u;
        u.x = *(unsigned*)&h01; u.y = *(unsigned*)&h23;
        u.z = *(unsigned*)&h45; u.w = *(unsigned*)&h67;
        *(uint4*)(smem + OFF_KT + j * 16) = u;
    } else {
        int i = tid - 256;
        __half2 h01 = __floats2half2_rn(q0[(0 << 16) + i], q0[(1 << 16) + i]);
        __half2 h23 = __floats2half2_rn(q0[(2 << 16) + i], q0[(3 << 16) + i]);
        __half2 h45 = __floats2half2_rn(q0[(4 << 16) + i], q0[(5 << 16) + i]);
        __half2 h67 = __floats2half2_rn(q0[(6 << 16) + i], q0[(7 << 16) + i]);
        uint4 u;
        u.x = *(unsigned*)&h01; u.y = *(unsigned*)&h23;
        u.z = *(unsigned*)&h45; u.w = *(unsigned*)&h67;
        *(uint4*)(smem + OFF_PT + i * 16) = u;
    }
    for (int idx = tid; idx < 8192; idx += 512) {
        int c = idx >> 7, h = idx & 127;
        float2 vv = *(const float2*)(v0 + (c << 16) + (h << 1));
        *(__half2*)(smem + OFF_V + c * 528 + h * 4) = __floats2half2_rn(vv.x, vv.y);
    }
    __syncthreads();

    int gid = lane >> 2, tid2 = lane & 3;

    // ---- max phase (m=i orientation): warp owns 16 i rows, max over all 256 j in regs ----
    {
        unsigned a0, a1;
        ldsm_x2(sbase + OFF_PT + (unsigned)((wid * 16 + (lane & 15)) * 16), a0, a1);
        float r0 = -1e30f, r2 = -1e30f;
        #pragma unroll
        for (int t = 0; t < 32; t++) {
            unsigned bb;
            ldsm_x1(sbase + OFF_KT + (unsigned)((t * 8 + (lane & 7)) * 16), bb);
            float d0, d1, d2, d3;
            mma16808(d0, d1, d2, d3, a0, a1, bb);
            r0 = fmaxf(r0, fmaxf(d0, d1));
            r2 = fmaxf(r2, fmaxf(d2, d3));
        }
        r0 = fmaxf(r0, __shfl_xor_sync(0xffffffffu, r0, 1));
        r0 = fmaxf(r0, __shfl_xor_sync(0xffffffffu, r0, 2));
        r2 = fmaxf(r2, __shfl_xor_sync(0xffffffffu, r2, 1));
        r2 = fmaxf(r2, __shfl_xor_sync(0xffffffffu, r2, 2));
        if (tid2 == 0) {
            __half* sm = (__half*)(smem + OFF_SMAX);
            sm[wid * 16 + gid]     = __float2half_rn(r0);
            sm[wid * 16 + gid + 8] = __float2half_rn(r2);
        }
    }
    __syncthreads();

    // ---- O-GEMM tiling (fixed across chunks) ----
    int mc = wid & 3, jc = wid >> 2;
    unsigned arow  = (unsigned)(mc * 16 + (lane & 7) + ((lane >> 3) & 1) * 8);
    unsigned abase = sbase + OFF_V + arow * 528u + (unsigned)(lane >> 4) * 16u;
    unsigned brow  = (unsigned)((lane & 7) + ((lane >> 4) ? 8 : 0));
    unsigned bbase = sbase + OFF_PT + ((unsigned)(jc * 64) + brow) * 272u
                   + (unsigned)((lane >> 3) & 1) * 16u;

    float acc[8][4];
    #pragma unroll
    for (int nt = 0; nt < 8; nt++)
        #pragma unroll
        for (int t = 0; t < 4; t++) acc[nt][t] = 0.f;

    // exp-phase A operand (kT rows for warp's 16 j) — constant across chunks
    unsigned pba0, pba1;
    ldsm_x2(sbase + OFF_KT + (unsigned)((wid * 16 + (lane & 15)) * 16), pba0, pba1);

    for (int chunk = 0; chunk < 2; chunk++) {
        // load qT chunk [128][8] fp16
        if (tid < 128) {
            int i = (chunk << 7) + tid;
            __half2 h01 = __floats2half2_rn(q0[(0 << 16) + i], q0[(1 << 16) + i]);
            __half2 h23 = __floats2half2_rn(q0[(2 << 16) + i], q0[(3 << 16) + i]);
            __half2 h45 = __floats2half2_rn(q0[(4 << 16) + i], q0[(5 << 16) + i]);
            __half2 h67 = __floats2half2_rn(q0[(6 << 16) + i], q0[(7 << 16) + i]);
            uint4 u;
            u.x = *(unsigned*)&h01; u.y = *(unsigned*)&h23;
            u.z = *(unsigned*)&h45; u.w = *(unsigned*)&h67;
            *(uint4*)(smem + OFF_QTC + tid * 16) = u;
        }
        __syncthreads();

        // ---- exp phase (m=j, n=i-chunk): P^T[j][i] = exp(S - m_i), col sums ----
        {
            const __half* smx = (const __half*)(smem + OFF_SMAX) + (chunk << 7);
            __half* pb = (__half*)(smem + OFF_PB);
            char* prow0 = smem + OFF_PT + (wid * 16 + gid) * 272 + tid2 * 4;
            char* prow8 = prow0 + 8 * 272;
            unsigned bq = sbase + OFF_QTC + (unsigned)((lane & 7) * 16);
            #pragma unroll
            for (int t = 0; t < 16; t++) {
                unsigned bb;
                ldsm_x1(bq + (unsigned)(t * 128), bb);
                float d0, d1, d2, d3;
                mma16808(d0, d1, d2, d3, pba0, pba1, bb);
                int iA = t * 8 + tid2 * 2;
                float mA = __half2float(smx[iA]);
                float mB = __half2float(smx[iA + 1]);
                float e0 = fexp(d0 - mA), e1 = fexp(d1 - mB);
                float e2 = fexp(d2 - mA), e3 = fexp(d3 - mB);
                *(__half2*)(prow0 + t * 16) = __floats2half2_rn(e0, e1);
                *(__half2*)(prow8 + t * 16) = __floats2half2_rn(e2, e3);
                float cs0 = e0 + e2, cs1 = e1 + e3;
                cs0 += __shfl_xor_sync(0xffffffffu, cs0, 4);
                cs0 += __shfl_xor_sync(0xffffffffu, cs0, 8);
                cs0 += __shfl_xor_sync(0xffffffffu, cs0, 16);
                cs1 += __shfl_xor_sync(0xffffffffu, cs1, 4);
                cs1 += __shfl_xor_sync(0xffffffffu, cs1, 8);
                cs1 += __shfl_xor_sync(0xffffffffu, cs1, 16);
                if (gid == 0)
                    *(__half2*)(pb + wid * 128 + iA) = __floats2half2_rn(cs0, cs1);
            }
        }
        __syncthreads();

        // reduce l partials -> 1/l
        if (tid < 128) {
            float s = 0.f;
            #pragma unroll
            for (int w = 0; w < 16; w++)
                s += __half2float(((__half*)(smem + OFF_PB))[w * 128 + tid]);
            ((float*)(smem + OFF_SL))[tid] = 1.0f / s;
        }
        __syncthreads();

        // fold 1/l_i into V's chunk columns
        {
            const float* sl = (const float*)(smem + OFF_SL);
            for (int idx = tid; idx < 4096; idx += 512) {
                int c = idx >> 6, hp = idx & 63;
                int i0 = hp << 1;
                __half2* vp = (__half2*)(smem + OFF_V + c * 528 + chunk * 256 + hp * 4);
                *vp = __hmul2(*vp, __floats2half2_rn(sl[i0], sl[i0 + 1]));
            }
        }
        __syncthreads();

        // O-GEMM K-chunk: acc += V'[c][k] * P^T[j][k]
        {
            unsigned aaddr = abase + (unsigned)chunk * 256u;
            #pragma unroll
            for (int kk = 0; kk < 8; kk++) {
                unsigned a0, a1, a2, a3;
                ldsm_x4(aaddr + (unsigned)kk * 32u, a0, a1, a2, a3);
                #pragma unroll
                for (int g = 0; g < 4; g++) {
                    unsigned b0, b1, b2, b3;
                    ldsm_x4(bbase + (unsigned)g * (16u * 272u) + (unsigned)kk * 32u,
                            b0, b1, b2, b3);
                    mma16816(acc[2 * g],     a0, a1, a2, a3, b0, b1);
                    mma16816(acc[2 * g + 1], a0, a1, a2, a3, b2, b3);
                }
            }
        }
        __syncthreads();   // protect PT before next chunk / O staging
    }

    // ---- stage O in smem (reuse PT as fp32 [c][stride 264]), coalesced store ----
    {
        float* so = (float*)(smem + OFF_PT);
        int crow = mc * 16 + gid;
        int jb2  = jc * 64 + tid2 * 2;
        #pragma unroll
        for (int nt = 0; nt < 8; nt++) {
            int j = jb2 + nt * 8;
            *(float2*)(so + crow * 264 + j)       = make_float2(acc[nt][0], acc[nt][1]);
            *(float2*)(so + (crow + 8) * 264 + j) = make_float2(acc[nt][2], acc[nt][3]);
        }
        __syncthreads();
        for (int idx = tid; idx < 4096; idx += 512) {
            int c  = idx >> 6;
            int j4 = (idx & 63) << 2;
            float4 val = *(const float4*)(so + c * 264 + j4);
            *(float4*)(o0 + (c << 16) + j4) = val;
        }
    }
}

// ---- K3: out = gamma*(h_out + w_out) + x, de-transposing g_hT on the fly ----
__global__ void combine_kernel(const float* __restrict__ x,
                               const float* __restrict__ gamma,
                               float* __restrict__ out)
{
    __shared__ float t[32][33];
    int plane = blockIdx.z;
    const float* hT = g_hT + ((long)plane << 16);
    const float* wf = g_w  + ((long)plane << 16);
    const float* xp = x    + ((long)plane << 16);
    float*       op = out  + ((long)plane << 16);
    int h0 = blockIdx.y << 5, w0 = blockIdx.x << 5;
    int tx = threadIdx.x, ty = threadIdx.y;
    float g = gamma[0];
    #pragma unroll
    for (int yy = 0; yy < 32; yy += 8)
        t[ty + yy][tx] = hT[(w0 + ty + yy) * 256 + h0 + tx];
    __syncthreads();
    #pragma unroll
    for (int yy = 0; yy < 32; yy += 8) {
        int idx = (h0 + ty + yy) * 256 + w0 + tx;
        op[idx] = fmaf(g, t[tx][ty + yy] + wf[idx], xp[idx]);
    }
}

extern "C" void kernel_launch(void* const* d_in, const int* in_sizes, int n_in,
                              void* d_out, int out_size) {
    const float* x     = (const float*)d_in[0];
    const float* Wq    = (const float*)d_in[1];
    const float* bq    = (const float*)d_in[2];
    const float* Wk    = (const float*)d_in[3];
    const float* bk    = (const float*)d_in[4];
    const float* Wv    = (const float*)d_in[5];
    const float* bv    = (const float*)d_in[6];
    const float* gamma = (const float*)d_in[7];
    float* out = (float*)d_out;

    cudaFuncSetAttribute(attn_kernel,
                         cudaFuncAttributeMaxDynamicSharedMemorySize, ATTN_SMEM);

    proj_kernel<<<2048, 256>>>(x, Wq, bq, Wk, bk, Wv, bv);
    transpose_all<<<dim3(8, 8, 640), dim3(32, 8)>>>();
    attn_kernel<<<4096, 512, ATTN_SMEM>>>();
    combine_kernel<<<dim3(8, 8, 512), dim3(32, 8)>>>(x, gamma, out);
}

// round 10
// speedup vs baseline: 2.5649x; 1.1401x over previous
#include <cuda_runtime.h>
#include <cuda_fp16.h>

#define HW 65536

// ---- scratch (device globals; all intermediates fp16) ----
__device__ __half g_qi [8 * HW * 8];    // [B][h*w][8c] interleaved
__device__ __half g_ki [8 * HW * 8];
__device__ __half g_qTi[8 * HW * 8];    // [B][w*h][8c]
__device__ __half g_kTi[8 * HW * 8];
__device__ __half g_v  [8 * 64 * HW];   // [B][C][h][w] planar
__device__ __half g_vT [8 * 64 * HW];   // [B][C][w][h]
__device__ __half g_hT [8 * 64 * HW];   // column-attn out, [B][C][w][h]
__device__ __half g_w  [8 * 64 * HW];   // row-attn out,    [B][C][h][w]

// ---- packed fp32x2 (proj) ----
__device__ __forceinline__ unsigned long long pk2(float lo, float hi) {
    unsigned long long r;
    asm("mov.b64 %0, {%1, %2};" : "=l"(r) : "f"(lo), "f"(hi));
    return r;
}
__device__ __forceinline__ float2 upk2(unsigned long long v) {
    float2 f;
    asm("mov.b64 {%0, %1}, %2;" : "=f"(f.x), "=f"(f.y) : "l"(v));
    return f;
}
__device__ __forceinline__ unsigned long long ffma2(unsigned long long a,
                                                    unsigned long long b,
                                                    unsigned long long c) {
    unsigned long long d;
    asm("fma.rn.f32x2 %0, %1, %2, %3;" : "=l"(d) : "l"(a), "l"(b), "l"(c));
    return d;
}

// ---- fast exp for bounded x on the FMA pipe (no MUFU) ----
__device__ __forceinline__ float fexp(float x) {
    x = fmaxf(x, -80.0f);
    const float L2E = 1.4426950408889634f;
    float t = fmaf(x, L2E, 12582912.0f);
    float n = t - 12582912.0f;
    float f = fmaf(x, L2E, -n);
    float p = fmaf(f, 0.0096181291f, 0.0555041087f);
    p = fmaf(f, p, 0.2402265069f);
    p = fmaf(f, p, 0.6931471806f);
    p = fmaf(f, p, 1.0f);
    return __int_as_float(__float_as_int(p) + (__float_as_int(t) << 23));
}

// ---- warp MMA helpers (baseline PTX: valid on plain sm_103 target) ----
__device__ __forceinline__ unsigned smem_u32(const void* p) {
    unsigned a;
    asm("{ .reg .u64 t; cvta.to.shared.u64 t, %1; cvt.u32.u64 %0, t; }"
        : "=r"(a) : "l"(p));
    return a;
}
__device__ __forceinline__ void ldsm_x4(unsigned addr, unsigned& r0, unsigned& r1,
                                        unsigned& r2, unsigned& r3) {
    asm volatile("ldmatrix.sync.aligned.m8n8.x4.shared.b16 {%0,%1,%2,%3}, [%4];"
                 : "=r"(r0), "=r"(r1), "=r"(r2), "=r"(r3) : "r"(addr));
}
__device__ __forceinline__ void ldsm_x2(unsigned addr, unsigned& r0, unsigned& r1) {
    asm volatile("ldmatrix.sync.aligned.m8n8.x2.shared.b16 {%0,%1}, [%2];"
                 : "=r"(r0), "=r"(r1) : "r"(addr));
}
__device__ __forceinline__ void mma16816(float* d, unsigned a0, unsigned a1,
                                         unsigned a2, unsigned a3,
                                         unsigned b0, unsigned b1) {
    asm volatile(
        "mma.sync.aligned.m16n8k16.row.col.f32.f16.f16.f32 "
        "{%0,%1,%2,%3},{%4,%5,%6,%7},{%8,%9},{%0,%1,%2,%3};"
        : "+f"(d[0]), "+f"(d[1]), "+f"(d[2]), "+f"(d[3])
        : "r"(a0), "r"(a1), "r"(a2), "r"(a3), "r"(b0), "r"(b1));
}
__device__ __forceinline__ void mma16808(float& d0, float& d1, float& d2, float& d3,
                                         unsigned a0, unsigned a1, unsigned b0) {
    asm volatile(
        "mma.sync.aligned.m16n8k8.row.col.f32.f16.f16.f32 "
        "{%0,%1,%2,%3},{%4,%5},{%6},{%7,%8,%9,%10};"
        : "=f"(d0), "=f"(d1), "=f"(d2), "=f"(d3)
        : "r"(a0), "r"(a1), "r"(b0),
          "f"(0.f), "f"(0.f), "f"(0.f), "f"(0.f));
}

// ---- K1: fused 1x1-conv projections; q/k interleaved uint4, v planar fp16 ----
__global__ __launch_bounds__(256) void proj_kernel(
    const float* __restrict__ x,
    const float* __restrict__ Wq, const float* __restrict__ bq,
    const float* __restrict__ Wk, const float* __restrict__ bk,
    const float* __restrict__ Wv, const float* __restrict__ bv)
{
    __shared__ float ws[64][80];
    __shared__ float bs[80];
    int tid = threadIdx.x;
    for (int idx = tid; idx < 64 * 80; idx += 256) {
        int c = idx / 80, o = idx % 80;
        float wv;
        if (o < 8)       wv = Wq[o * 64 + c];
        else if (o < 16) wv = Wk[(o - 8) * 64 + c];
        else             wv = Wv[(o - 16) * 64 + c];
        ws[c][o] = wv;
    }
    if (tid < 80) bs[tid] = (tid < 8) ? bq[tid] : (tid < 16 ? bk[tid - 8] : bv[tid - 16]);
    __syncthreads();

    int p  = blockIdx.x * 256 + tid;
    int b  = p >> 16;
    int hw = p & 65535;
    const float* xp = x + ((long)(b * 64) << 16) + hw;

    unsigned long long av[40];
    #pragma unroll
    for (int o = 0; o < 40; o++) av[o] = pk2(bs[2 * o], bs[2 * o + 1]);

    #pragma unroll 4
    for (int c = 0; c < 64; c++) {
        float xv = xp[c << 16];
        unsigned long long x2 = pk2(xv, xv);
        const unsigned long long* wr = (const unsigned long long*)(&ws[c][0]);
        #pragma unroll
        for (int o = 0; o < 40; o++) av[o] = ffma2(wr[o], x2, av[o]);
    }

    // q: outputs 0..7 -> one uint4
    {
        uint4 u;
        float2 f0 = upk2(av[0]), f1 = upk2(av[1]), f2 = upk2(av[2]), f3 = upk2(av[3]);
        __half2 h0 = __floats2half2_rn(f0.x, f0.y);
        __half2 h1 = __floats2half2_rn(f1.x, f1.y);
        __half2 h2 = __floats2half2_rn(f2.x, f2.y);
        __half2 h3 = __floats2half2_rn(f3.x, f3.y);
        u.x = *(unsigned*)&h0; u.y = *(unsigned*)&h1;
        u.z = *(unsigned*)&h2; u.w = *(unsigned*)&h3;
        ((uint4*)g_qi)[p] = u;
    }
    // k: outputs 8..15
    {
        uint4 u;
        float2 f0 = upk2(av[4]), f1 = upk2(av[5]), f2 = upk2(av[6]), f3 = upk2(av[7]);
        __half2 h0 = __floats2half2_rn(f0.x, f0.y);
        __half2 h1 = __floats2half2_rn(f1.x, f1.y);
        __half2 h2 = __floats2half2_rn(f2.x, f2.y);
        __half2 h3 = __floats2half2_rn(f3.x, f3.y);
        u.x = *(unsigned*)&h0; u.y = *(unsigned*)&h1;
        u.z = *(unsigned*)&h2; u.w = *(unsigned*)&h3;
        ((uint4*)g_ki)[p] = u;
    }
    // v: outputs 16..79 -> planar fp16
    #pragma unroll
    for (int o2 = 8; o2 < 40; o2++) {
        float2 f = upk2(av[o2]);
        int c = (o2 - 8) * 2;
        g_v[((b * 64 + c    ) << 16) + hw] = __float2half_rn(f.x);
        g_v[((b * 64 + c + 1) << 16) + hw] = __float2half_rn(f.y);
    }
}

// ---- K1b-a: transpose interleaved q/k (uint4 elements, 16x16 tiles) ----
__global__ void transpose_qk()   // grid (16,16,16), block (16,16)
{
    __shared__ uint4 t[16][17];
    int img = blockIdx.z;
    const uint4* s = (img < 8) ? (const uint4*)g_qi + (long)img * HW
                               : (const uint4*)g_ki + (long)(img - 8) * HW;
    uint4* d = (img < 8) ? (uint4*)g_qTi + (long)img * HW
                         : (uint4*)g_kTi + (long)(img - 8) * HW;
    int x0 = blockIdx.x << 4, y0 = blockIdx.y << 4;
    t[threadIdx.y][threadIdx.x] = s[(y0 + threadIdx.y) * 256 + x0 + threadIdx.x];
    __syncthreads();
    d[(x0 + threadIdx.y) * 256 + y0 + threadIdx.x] = t[threadIdx.x][threadIdx.y];
}

// ---- K1b-b: transpose v planes (fp16, 64x64 tiles) ----
__global__ void transpose_v()    // grid (4,4,512), block 256
{
    __shared__ __half s[64][66];
    int p = blockIdx.z;
    const __half* src = g_v  + ((long)p << 16);
    __half*       dst = g_vT + ((long)p << 16);
    int x0 = blockIdx.x << 6, y0 = blockIdx.y << 6;
    int t = threadIdx.x;
    int c2 = (t & 31) * 2, r0 = t >> 5;
    #pragma unroll
    for (int rr = 0; rr < 8; rr++) {
        int row = r0 + rr * 8;
        __half2 v = *(const __half2*)(src + (y0 + row) * 256 + x0 + c2);
        s[c2][row]     = __low2half(v);
        s[c2 + 1][row] = __high2half(v);
    }
    __syncthreads();
    #pragma unroll
    for (int rr = 0; rr < 8; rr++) {
        int row = r0 + rr * 8;
        *(__half2*)(dst + (x0 + row) * 256 + y0 + c2) = *(const __half2*)(&s[row][c2]);
    }
}

// ---- K2: line attention; QK + O on tensor cores; fp16 I/O ----
// smem (bytes), total 114688 -> 2 CTAs/SM:
#define OFF_KT   0        // fp16 kT [j=256][c=8], 16B rows          (4096)
#define OFF_QTC  4096     // fp16 qT chunk [i=128][c=8], 16B rows    (2048)
#define OFF_V    6144     // fp16 V [c=64][stride 264 halfs]         (33792)
#define OFF_PT   39936    // fp16 P^T [j=256][stride 272B]           (69632)
                          //   (also: qT-full borrow in max phase; fp16 O staging)
#define OFF_PB   109568   // fp16 l-partials [16][128]               (4096)
#define OFF_SMAX 113664   // fp16 [256]                              (512)
#define OFF_SL   114176   // fp32 [128]                              (512)
#define ATTN_SMEM 114688

__global__ __launch_bounds__(512, 2) void attn_kernel()
{
    extern __shared__ char smem[];
    unsigned sbase = smem_u32(smem);

    int mode = blockIdx.x >> 11;
    int n    = blockIdx.x & 2047;
    int b    = n >> 8, line = n & 255;

    const uint4* qi = ((mode == 0) ? (const uint4*)g_qi : (const uint4*)g_qTi)
                    + (long)b * HW + line * 256;
    const uint4* ki = ((mode == 0) ? (const uint4*)g_ki : (const uint4*)g_kTi)
                    + (long)b * HW + line * 256;
    const __half* v0 = ((mode == 0) ? g_v : g_vT) + ((long)(b * 64) << 16) + (line << 8);
    __half*       o0 = ((mode == 0) ? g_w : g_hT) + ((long)(b * 64) << 16) + (line << 8);

    int tid  = threadIdx.x;
    int wid  = tid >> 5;
    int lane = tid & 31;
    int gid = lane >> 2, tid2 = lane & 3;

    // ---- loads: kT copy (tid<256), qT-full borrow (tid>=256), V copy (all) ----
    if (tid < 256) {
        ((uint4*)(smem + OFF_KT))[tid] = ki[tid];
    } else {
        ((uint4*)(smem + OFF_PT))[tid - 256] = qi[tid - 256];
    }
    for (int idx = tid; idx < 2048; idx += 512) {
        int c = idx >> 5, seg = idx & 31;
        *(uint4*)(smem + OFF_V + c * 528 + seg * 16) =
            ((const uint4*)(v0 + (c << 16)))[seg];
    }
    __syncthreads();

    // ---- max phase (m=i): warp owns 16 i rows; batched ldsm_x4 on B ----
    {
        unsigned a0, a1;
        ldsm_x2(sbase + OFF_PT + (unsigned)((wid * 16 + (lane & 15)) * 16), a0, a1);
        float r0 = -1e30f, r2 = -1e30f;
        #pragma unroll
        for (int t4 = 0; t4 < 8; t4++) {
            unsigned b0, b1, b2, b3;
            ldsm_x4(sbase + OFF_KT + (unsigned)((t4 * 32 + lane) * 16), b0, b1, b2, b3);
            #pragma unroll
            for (int tt = 0; tt < 4; tt++) {
                unsigned bb = (tt == 0) ? b0 : (tt == 1) ? b1 : (tt == 2) ? b2 : b3;
                float d0, d1, d2, d3;
                mma16808(d0, d1, d2, d3, a0, a1, bb);
                r0 = fmaxf(r0, fmaxf(d0, d1));
                r2 = fmaxf(r2, fmaxf(d2, d3));
            }
        }
        r0 = fmaxf(r0, __shfl_xor_sync(0xffffffffu, r0, 1));
        r0 = fmaxf(r0, __shfl_xor_sync(0xffffffffu, r0, 2));
        r2 = fmaxf(r2, __shfl_xor_sync(0xffffffffu, r2, 1));
        r2 = fmaxf(r2, __shfl_xor_sync(0xffffffffu, r2, 2));
        if (tid2 == 0) {
            __half* sm = (__half*)(smem + OFF_SMAX);
            sm[wid * 16 + gid]     = __float2half_rn(r0);
            sm[wid * 16 + gid + 8] = __float2half_rn(r2);
        }
    }
    __syncthreads();

    // ---- O-GEMM tiling (fixed across chunks) ----
    int mc = wid & 3, jc = wid >> 2;
    unsigned arow  = (unsigned)(mc * 16 + (lane & 7) + ((lane >> 3) & 1) * 8);
    unsigned abase = sbase + OFF_V + arow * 528u + (unsigned)(lane >> 4) * 16u;
    unsigned brow  = (unsigned)((lane & 7) + ((lane >> 4) ? 8 : 0));
    unsigned bbase = sbase + OFF_PT + ((unsigned)(jc * 64) + brow) * 272u
                   + (unsigned)((lane >> 3) & 1) * 16u;

    float acc[8][4];
    #pragma unroll
    for (int nt = 0; nt < 8; nt++)
        #pragma unroll
        for (int t = 0; t < 4; t++) acc[nt][t] = 0.f;

    // exp-phase A operand (kT rows for warp's 16 j) — constant across chunks
    unsigned pba0, pba1;
    ldsm_x2(sbase + OFF_KT + (unsigned)((wid * 16 + (lane & 15)) * 16), pba0, pba1);

    for (int chunk = 0; chunk < 2; chunk++) {
        if (tid < 128)
            ((uint4*)(smem + OFF_QTC))[tid] = qi[(chunk << 7) + tid];
        __syncthreads();

        // ---- exp phase (m=j, n=i): P^T[j][i] = exp(S - m_i); col sums ----
        {
            const __half* smx = (const __half*)(smem + OFF_SMAX) + (chunk << 7);
            __half* pb = (__half*)(smem + OFF_PB);
            char* prow0 = smem + OFF_PT + (wid * 16 + gid) * 272 + tid2 * 4;
            char* prow8 = prow0 + 8 * 272;
            #pragma unroll
            for (int t4 = 0; t4 < 4; t4++) {
                unsigned b0, b1, b2, b3;
                ldsm_x4(sbase + OFF_QTC + (unsigned)((t4 * 32 + lane) * 16),
                        b0, b1, b2, b3);
                #pragma unroll
                for (int tt = 0; tt < 4; tt++) {
                    unsigned bb = (tt == 0) ? b0 : (tt == 1) ? b1 : (tt == 2) ? b2 : b3;
                    int t = t4 * 4 + tt;
                    float d0, d1, d2, d3;
                    mma16808(d0, d1, d2, d3, pba0, pba1, bb);
                    int iA = t * 8 + tid2 * 2;
                    float mA = __half2float(smx[iA]);
                    float mB = __half2float(smx[iA + 1]);
                    float e0 = fexp(d0 - mA), e1 = fexp(d1 - mB);
                    float e2 = fexp(d2 - mA), e3 = fexp(d3 - mB);
                    *(__half2*)(prow0 + t * 16) = __floats2half2_rn(e0, e1);
                    *(__half2*)(prow8 + t * 16) = __floats2half2_rn(e2, e3);
                    float cs0 = e0 + e2, cs1 = e1 + e3;
                    cs0 += __shfl_xor_sync(0xffffffffu, cs0, 4);
                    cs0 += __shfl_xor_sync(0xffffffffu, cs0, 8);
                    cs0 += __shfl_xor_sync(0xffffffffu, cs0, 16);
                    cs1 += __shfl_xor_sync(0xffffffffu, cs1, 4);
                    cs1 += __shfl_xor_sync(0xffffffffu, cs1, 8);
                    cs1 += __shfl_xor_sync(0xffffffffu, cs1, 16);
                    if (gid == 0)
                        *(__half2*)(pb + wid * 128 + iA) = __floats2half2_rn(cs0, cs1);
                }
            }
        }
        __syncthreads();

        // reduce l partials -> 1/l
        if (tid < 128) {
            float s = 0.f;
            #pragma unroll
            for (int w = 0; w < 16; w++)
                s += __half2float(((__half*)(smem + OFF_PB))[w * 128 + tid]);
            ((float*)(smem + OFF_SL))[tid] = 1.0f / s;
        }
        __syncthreads();

        // fold 1/l_i into V's chunk columns
        {
            const float* sl = (const float*)(smem + OFF_SL);
            for (int idx = tid; idx < 4096; idx += 512) {
                int c = idx >> 6, hp = idx & 63;
                int i0 = hp << 1;
                __half2* vp = (__half2*)(smem + OFF_V + c * 528 + chunk * 256 + hp * 4);
                *vp = __hmul2(*vp, __floats2half2_rn(sl[i0], sl[i0 + 1]));
            }
        }
        __syncthreads();

        // O-GEMM K-chunk: acc += V'[c][k] * P^T[j][k]
        {
            unsigned aaddr = abase + (unsigned)chunk * 256u;
            #pragma unroll
            for (int kk = 0; kk < 8; kk++) {
                unsigned a0, a1, a2, a3;
                ldsm_x4(aaddr + (unsigned)kk * 32u, a0, a1, a2, a3);
                #pragma unroll
                for (int g = 0; g < 4; g++) {
                    unsigned b0, b1, b2, b3;
                    ldsm_x4(bbase + (unsigned)g * (16u * 272u) + (unsigned)kk * 32u,
                            b0, b1, b2, b3);
                    mma16816(acc[2 * g],     a0, a1, a2, a3, b0, b1);
                    mma16816(acc[2 * g + 1], a0, a1, a2, a3, b2, b3);
                }
            }
        }
        __syncthreads();
    }

    // ---- stage O fp16 in smem (reuse PT, stride 264 halfs), coalesced store ----
    {
        __half* so = (__half*)(smem + OFF_PT);
        int crow = mc * 16 + gid;
        int jb2  = jc * 64 + tid2 * 2;
        #pragma unroll
        for (int nt = 0; nt < 8; nt++) {
            int j = jb2 + nt * 8;
            *(__half2*)(so + crow * 264 + j)       = __floats2half2_rn(acc[nt][0], acc[nt][1]);
            *(__half2*)(so + (crow + 8) * 264 + j) = __floats2half2_rn(acc[nt][2], acc[nt][3]);
        }
        __syncthreads();
        // FIXED: 256 halfs per row = 32 uint4 (round 9 wrote only 16 -> half the
        // output stayed poisoned; that was the 2.3e-2 rel_err)
        for (int idx = tid; idx < 2048; idx += 512) {
            int c = idx >> 5, seg = idx & 31;
            ((uint4*)(o0 + (c << 16)))[seg] = *(uint4*)(so + c * 264 + seg * 8);
        }
    }
}

// ---- K3: out = gamma*(h_out + w_out) + x (fp16 h/w, fp32 out) ----
__global__ void combine_kernel(const float* __restrict__ x,
                               const float* __restrict__ gamma,
                               float* __restrict__ out)
{
    __shared__ __half t[32][33];
    int plane = blockIdx.z;
    const __half* hT = g_hT + ((long)plane << 16);
    const __half* wf = g_w  + ((long)plane << 16);
    const float*  xp = x    + ((long)plane << 16);
    float*        op = out  + ((long)plane << 16);
    int h0 = blockIdx.y << 5, w0 = blockIdx.x << 5;
    int tx = threadIdx.x, ty = threadIdx.y;
    float g = gamma[0];
    #pragma unroll
    for (int yy = 0; yy < 32; yy += 8)
        t[ty + yy][tx] = hT[(w0 + ty + yy) * 256 + h0 + tx];
    __syncthreads();
    #pragma unroll
    for (int yy = 0; yy < 32; yy += 8) {
        int idx = (h0 + ty + yy) * 256 + w0 + tx;
        op[idx] = fmaf(g, __half2float(t[tx][ty + yy]) + __half2float(wf[idx]), xp[idx]);
    }
}

extern "C" void kernel_launch(void* const* d_in, const int* in_sizes, int n_in,
                              void* d_out, int out_size) {
    const float* x     = (const float*)d_in[0];
    const float* Wq    = (const float*)d_in[1];
    const float* bq    = (const float*)d_in[2];
    const float* Wk    = (const float*)d_in[3];
    const float* bk    = (const float*)d_in[4];
    const float* Wv    = (const float*)d_in[5];
    const float* bv    = (const float*)d_in[6];
    const float* gamma = (const float*)d_in[7];
    float* out = (float*)d_out;

    cudaFuncSetAttribute(attn_kernel,
                         cudaFuncAttributeMaxDynamicSharedMemorySize, ATTN_SMEM);

    proj_kernel<<<2048, 256>>>(x, Wq, bq, Wk, bk, Wv, bv);
    transpose_qk<<<dim3(16, 16, 16), dim3(16, 16)>>>();
    transpose_v<<<dim3(4, 4, 512), 256>>>();
    attn_kernel<<<4096, 512, ATTN_SMEM>>>();
    combine_kernel<<<dim3(8, 8, 512), dim3(32, 8)>>>(x, gamma, out);
}

// round 13
// speedup vs baseline: 2.7814x; 1.0844x over previous
#include <cuda_runtime.h>
#include <cuda_fp16.h>

#define HW 65536

// ---- scratch (device globals; all intermediates fp16) ----
__device__ __half g_qi [8 * HW * 8];    // [B][h*w][8c] interleaved
__device__ __half g_ki [8 * HW * 8];
__device__ __half g_qTi[8 * HW * 8];    // [B][w*h][8c]
__device__ __half g_kTi[8 * HW * 8];
__device__ __half g_v  [8 * 64 * HW];   // [B][C][h][w] planar
__device__ __half g_vT [8 * 64 * HW];   // [B][C][w][h]
__device__ __half g_hT [8 * 64 * HW];   // column-attn out, [B][C][w][h]
__device__ __half g_w  [8 * 64 * HW];   // row-attn out,    [B][C][h][w]

// ---- packed fp32x2 (proj) ----
__device__ __forceinline__ unsigned long long pk2(float lo, float hi) {
    unsigned long long r;
    asm("mov.b64 %0, {%1, %2};" : "=l"(r) : "f"(lo), "f"(hi));
    return r;
}
__device__ __forceinline__ float2 upk2(unsigned long long v) {
    float2 f;
    asm("mov.b64 {%0, %1}, %2;" : "=f"(f.x), "=f"(f.y) : "l"(v));
    return f;
}
__device__ __forceinline__ unsigned long long ffma2(unsigned long long a,
                                                    unsigned long long b,
                                                    unsigned long long c) {
    unsigned long long d;
    asm("fma.rn.f32x2 %0, %1, %2, %3;" : "=l"(d) : "l"(a), "l"(b), "l"(c));
    return d;
}

// ---- warp MMA helpers (baseline PTX: valid on plain sm_103 target) ----
__device__ __forceinline__ unsigned smem_u32(const void* p) {
    unsigned a;
    asm("{ .reg .u64 t; cvta.to.shared.u64 t, %1; cvt.u32.u64 %0, t; }"
        : "=r"(a) : "l"(p));
    return a;
}
__device__ __forceinline__ void ldsm_x4(unsigned addr, unsigned& r0, unsigned& r1,
                                        unsigned& r2, unsigned& r3) {
    asm volatile("ldmatrix.sync.aligned.m8n8.x4.shared.b16 {%0,%1,%2,%3}, [%4];"
                 : "=r"(r0), "=r"(r1), "=r"(r2), "=r"(r3) : "r"(addr));
}
__device__ __forceinline__ void ldsm_x2(unsigned addr, unsigned& r0, unsigned& r1) {
    asm volatile("ldmatrix.sync.aligned.m8n8.x2.shared.b16 {%0,%1}, [%2];"
                 : "=r"(r0), "=r"(r1) : "r"(addr));
}
__device__ __forceinline__ void mma16816(float* d, unsigned a0, unsigned a1,
                                         unsigned a2, unsigned a3,
                                         unsigned b0, unsigned b1) {
    asm volatile(
        "mma.sync.aligned.m16n8k16.row.col.f32.f16.f16.f32 "
        "{%0,%1,%2,%3},{%4,%5,%6,%7},{%8,%9},{%0,%1,%2,%3};"
        : "+f"(d[0]), "+f"(d[1]), "+f"(d[2]), "+f"(d[3])
        : "r"(a0), "r"(a1), "r"(a2), "r"(a3), "r"(b0), "r"(b1));
}
__device__ __forceinline__ void mma16808(float& d0, float& d1, float& d2, float& d3,
                                         unsigned a0, unsigned a1, unsigned b0) {
    asm volatile(
        "mma.sync.aligned.m16n8k8.row.col.f32.f16.f16.f32 "
        "{%0,%1,%2,%3},{%4,%5},{%6},{%7,%8,%9,%10};"
        : "=f"(d0), "=f"(d1), "=f"(d2), "=f"(d3)
        : "r"(a0), "r"(a1), "r"(b0),
          "f"(0.f), "f"(0.f), "f"(0.f), "f"(0.f));
}
__device__ __forceinline__ unsigned ex2_f16x2(unsigned x) {
    unsigned r;
    asm("ex2.approx.f16x2 %0, %1;" : "=r"(r) : "r"(x));
    return r;
}

// ---- K1: fused 1x1-conv projections; q/k interleaved uint4, v planar fp16 ----
__global__ __launch_bounds__(256) void proj_kernel(
    const float* __restrict__ x,
    const float* __restrict__ Wq, const float* __restrict__ bq,
    const float* __restrict__ Wk, const float* __restrict__ bk,
    const float* __restrict__ Wv, const float* __restrict__ bv)
{
    __shared__ float ws[64][80];
    __shared__ float bs[80];
    int tid = threadIdx.x;
    for (int idx = tid; idx < 64 * 80; idx += 256) {
        int c = idx / 80, o = idx % 80;
        float wv;
        if (o < 8)       wv = Wq[o * 64 + c];
        else if (o < 16) wv = Wk[(o - 8) * 64 + c];
        else             wv = Wv[(o - 16) * 64 + c];
        ws[c][o] = wv;
    }
    if (tid < 80) bs[tid] = (tid < 8) ? bq[tid] : (tid < 16 ? bk[tid - 8] : bv[tid - 16]);
    __syncthreads();

    int p  = blockIdx.x * 256 + tid;
    int b  = p >> 16;
    int hw = p & 65535;
    const float* xp = x + ((long)(b * 64) << 16) + hw;

    unsigned long long av[40];
    #pragma unroll
    for (int o = 0; o < 40; o++) av[o] = pk2(bs[2 * o], bs[2 * o + 1]);

    #pragma unroll 4
    for (int c = 0; c < 64; c++) {
        float xv = xp[c << 16];
        unsigned long long x2 = pk2(xv, xv);
        const unsigned long long* wr = (const unsigned long long*)(&ws[c][0]);
        #pragma unroll
        for (int o = 0; o < 40; o++) av[o] = ffma2(wr[o], x2, av[o]);
    }

    // q: outputs 0..7 -> one uint4
    {
        uint4 u;
        float2 f0 = upk2(av[0]), f1 = upk2(av[1]), f2 = upk2(av[2]), f3 = upk2(av[3]);
        __half2 h0 = __floats2half2_rn(f0.x, f0.y);
        __half2 h1 = __floats2half2_rn(f1.x, f1.y);
        __half2 h2 = __floats2half2_rn(f2.x, f2.y);
        __half2 h3 = __floats2half2_rn(f3.x, f3.y);
        u.x = *(unsigned*)&h0; u.y = *(unsigned*)&h1;
        u.z = *(unsigned*)&h2; u.w = *(unsigned*)&h3;
        ((uint4*)g_qi)[p] = u;
    }
    // k: outputs 8..15
    {
        uint4 u;
        float2 f0 = upk2(av[4]), f1 = upk2(av[5]), f2 = upk2(av[6]), f3 = upk2(av[7]);
        __half2 h0 = __floats2half2_rn(f0.x, f0.y);
        __half2 h1 = __floats2half2_rn(f1.x, f1.y);
        __half2 h2 = __floats2half2_rn(f2.x, f2.y);
        __half2 h3 = __floats2half2_rn(f3.x, f3.y);
        u.x = *(unsigned*)&h0; u.y = *(unsigned*)&h1;
        u.z = *(unsigned*)&h2; u.w = *(unsigned*)&h3;
        ((uint4*)g_ki)[p] = u;
    }
    // v: outputs 16..79 -> planar fp16
    #pragma unroll
    for (int o2 = 8; o2 < 40; o2++) {
        float2 f = upk2(av[o2]);
        int c = (o2 - 8) * 2;
        g_v[((b * 64 + c    ) << 16) + hw] = __float2half_rn(f.x);
        g_v[((b * 64 + c + 1) << 16) + hw] = __float2half_rn(f.y);
    }
}

// ---- K1b-a: transpose interleaved q/k (uint4 elements, 16x16 tiles) ----
__global__ void transpose_qk()   // grid (16,16,16), block (16,16)
{
    __shared__ uint4 t[16][17];
    int img = blockIdx.z;
    const uint4* s = (img < 8) ? (const uint4*)g_qi + (long)img * HW
                               : (const uint4*)g_ki + (long)(img - 8) * HW;
    uint4* d = (img < 8) ? (uint4*)g_qTi + (long)img * HW
                         : (uint4*)g_kTi + (long)(img - 8) * HW;
    int x0 = blockIdx.x << 4, y0 = blockIdx.y << 4;
    t[threadIdx.y][threadIdx.x] = s[(y0 + threadIdx.y) * 256 + x0 + threadIdx.x];
    __syncthreads();
    d[(x0 + threadIdx.y) * 256 + y0 + threadIdx.x] = t[threadIdx.x][threadIdx.y];
}

// ---- K1b-b: transpose v planes (fp16, 64x64 tiles) ----
__global__ void transpose_v()    // grid (4,4,512), block 256
{
    __shared__ __half s[64][66];
    int p = blockIdx.z;
    const __half* src = g_v  + ((long)p << 16);
    __half*       dst = g_vT + ((long)p << 16);
    int x0 = blockIdx.x << 6, y0 = blockIdx.y << 6;
    int t = threadIdx.x;
    int c2 = (t & 31) * 2, r0 = t >> 5;
    #pragma unroll
    for (int rr = 0; rr < 8; rr++) {
        int row = r0 + rr * 8;
        __half2 v = *(const __half2*)(src + (y0 + row) * 256 + x0 + c2);
        s[c2][row]     = __low2half(v);
        s[c2 + 1][row] = __high2half(v);
    }
    __syncthreads();
    #pragma unroll
    for (int rr = 0; rr < 8; rr++) {
        int row = r0 + rr * 8;
        *(__half2*)(dst + (x0 + row) * 256 + y0 + c2) = *(const __half2*)(&s[row][c2]);
    }
}

// ---- K2: line attention; MMA max + ex2 exp + HMMA GEMMs ----
// smem (bytes), total 114688 -> 2 CTAs/SM:
#define OFF_KT   0        // fp16 kT [j=256][c=8], 16B rows          (4096)
#define OFF_QTC  4096     // fp16 qT chunk [i=128][c=8], 16B rows    (2048)
#define OFF_V    6144     // fp16 V [c=64][stride 264 halfs]         (33792)
#define OFF_PT   39936    // fp16 P^T [j=256][stride 272B]           (69632)
                          //   (also: qT-full borrow in max phase; fp16 O staging)
#define OFF_PB   109568   // fp16 l-partials [16][128]               (4096)
#define OFF_SMAX 113664   // fp16 m*log2e [256]                      (512)
#define OFF_SL   114176   // fp32 1/l [128]                          (512)
#define ATTN_SMEM 114688

__global__ __launch_bounds__(512, 2) void attn_kernel()
{
    extern __shared__ char smem[];
    unsigned sbase = smem_u32(smem);

    int mode = blockIdx.x >> 11;
    int n    = blockIdx.x & 2047;
    int b    = n >> 8, line = n & 255;

    const uint4* qi = ((mode == 0) ? (const uint4*)g_qi : (const uint4*)g_qTi)
                    + (long)b * HW + line * 256;
    const uint4* ki = ((mode == 0) ? (const uint4*)g_ki : (const uint4*)g_kTi)
                    + (long)b * HW + line * 256;
    const __half* v0 = ((mode == 0) ? g_v : g_vT) + ((long)(b * 64) << 16) + (line << 8);
    __half*       o0 = ((mode == 0) ? g_w : g_hT) + ((long)(b * 64) << 16) + (line << 8);

    int tid  = threadIdx.x;
    int wid  = tid >> 5;
    int lane = tid & 31;
    int gid = lane >> 2, tid2 = lane & 3;
    const float L2E = 1.4426950408889634f;

    // ---- loads: kT copy (tid<256), qT-full borrow (tid>=256), V copy (all) ----
    if (tid < 256) {
        ((uint4*)(smem + OFF_KT))[tid] = ki[tid];
    } else {
        ((uint4*)(smem + OFF_PT))[tid - 256] = qi[tid - 256];
    }
    for (int idx = tid; idx < 2048; idx += 512) {
        int c = idx >> 5, seg = idx & 31;
        *(uint4*)(smem + OFF_V + c * 528 + seg * 16) =
            ((const uint4*)(v0 + (c << 16)))[seg];
    }
    __syncthreads();

    // ---- max phase (m=i): warp owns 16 i rows; true row max in registers ----
    // (round-11's analytic Hoelder bound underflowed fp16 P -> NaN; true max
    //  centers P at 1.0 which is exactly what fp16 storage needs)
    {
        unsigned a0, a1;
        ldsm_x2(sbase + OFF_PT + (unsigned)((wid * 16 + (lane & 15)) * 16), a0, a1);
        float r0 = -1e30f, r2 = -1e30f;
        #pragma unroll
        for (int t4 = 0; t4 < 8; t4++) {
            unsigned b0, b1, b2, b3;
            ldsm_x4(sbase + OFF_KT + (unsigned)((t4 * 32 + lane) * 16), b0, b1, b2, b3);
            #pragma unroll
            for (int tt = 0; tt < 4; tt++) {
                unsigned bb = (tt == 0) ? b0 : (tt == 1) ? b1 : (tt == 2) ? b2 : b3;
                float d0, d1, d2, d3;
                mma16808(d0, d1, d2, d3, a0, a1, bb);
                r0 = fmaxf(r0, fmaxf(d0, d1));
                r2 = fmaxf(r2, fmaxf(d2, d3));
            }
        }
        r0 = fmaxf(r0, __shfl_xor_sync(0xffffffffu, r0, 1));
        r0 = fmaxf(r0, __shfl_xor_sync(0xffffffffu, r0, 2));
        r2 = fmaxf(r2, __shfl_xor_sync(0xffffffffu, r2, 1));
        r2 = fmaxf(r2, __shfl_xor_sync(0xffffffffu, r2, 2));
        if (tid2 == 0) {
            __half* sm = (__half*)(smem + OFF_SMAX);
            sm[wid * 16 + gid]     = __float2half_rn(r0 * L2E);
            sm[wid * 16 + gid + 8] = __float2half_rn(r2 * L2E);
        }
    }
    __syncthreads();

    // ---- O-GEMM tiling (fixed across chunks) ----
    int mc = wid & 3, jc = wid >> 2;
    unsigned arow  = (unsigned)(mc * 16 + (lane & 7) + ((lane >> 3) & 1) * 8);
    unsigned abase = sbase + OFF_V + arow * 528u + (unsigned)(lane >> 4) * 16u;
    unsigned brow  = (unsigned)((lane & 7) + ((lane >> 4) ? 8 : 0));
    unsigned bbase = sbase + OFF_PT + ((unsigned)(jc * 64) + brow) * 272u
                   + (unsigned)((lane >> 3) & 1) * 16u;

    float acc[8][4];
    #pragma unroll
    for (int nt = 0; nt < 8; nt++)
        #pragma unroll
        for (int t = 0; t < 4; t++) acc[nt][t] = 0.f;

    // exp-phase A operand (kT rows for warp's 16 j) — constant across chunks
    unsigned pba0, pba1;
    ldsm_x2(sbase + OFF_KT + (unsigned)((wid * 16 + (lane & 15)) * 16), pba0, pba1);

    for (int chunk = 0; chunk < 2; chunk++) {
        if (tid < 128)
            ((uint4*)(smem + OFF_QTC))[tid] = qi[(chunk << 7) + tid];
        __syncthreads();

        // ---- exp phase (m=j, n=i): P^T[j][i] = 2^(S*l2e - m*l2e); col sums ----
        {
            const __half* smx = (const __half*)(smem + OFF_SMAX) + (chunk << 7);
            __half* pb = (__half*)(smem + OFF_PB);
            char* prow0 = smem + OFF_PT + (wid * 16 + gid) * 272 + tid2 * 4;
            char* prow8 = prow0 + 8 * 272;
            #pragma unroll
            for (int t4 = 0; t4 < 4; t4++) {
                unsigned b0, b1, b2, b3;
                ldsm_x4(sbase + OFF_QTC + (unsigned)((t4 * 32 + lane) * 16),
                        b0, b1, b2, b3);
                #pragma unroll
                for (int tt = 0; tt < 4; tt++) {
                    unsigned bb = (tt == 0) ? b0 : (tt == 1) ? b1 : (tt == 2) ? b2 : b3;
                    int t = t4 * 4 + tt;
                    float d0, d1, d2, d3;
                    mma16808(d0, d1, d2, d3, pba0, pba1, bb);
                    int iA = t * 8 + tid2 * 2;
                    float2 mf = __half22float2(*(const __half2*)(smx + iA));
                    float f0 = fmaf(d0, L2E, -mf.x);
                    float f1 = fmaf(d1, L2E, -mf.y);
                    float f2 = fmaf(d2, L2E, -mf.x);
                    float f3 = fmaf(d3, L2E, -mf.y);
                    __half2 h01 = __floats2half2_rn(f0, f1);
                    __half2 h23 = __floats2half2_rn(f2, f3);
                    unsigned e01 = ex2_f16x2(*(unsigned*)&h01);
                    unsigned e23 = ex2_f16x2(*(unsigned*)&h23);
                    *(unsigned*)(prow0 + t * 16) = e01;
                    *(unsigned*)(prow8 + t * 16) = e23;
                    // packed col sums over this warp's 16 rows
                    __half2 cs = __hadd2(*(__half2*)&e01, *(__half2*)&e23);
                    unsigned csu = *(unsigned*)&cs;
                    unsigned o4  = __shfl_xor_sync(0xffffffffu, csu, 4);
                    cs = __hadd2(cs, *(__half2*)&o4);  csu = *(unsigned*)&cs;
                    unsigned o8  = __shfl_xor_sync(0xffffffffu, csu, 8);
                    cs = __hadd2(cs, *(__half2*)&o8);  csu = *(unsigned*)&cs;
                    unsigned o16 = __shfl_xor_sync(0xffffffffu, csu, 16);
                    cs = __hadd2(cs, *(__half2*)&o16); csu = *(unsigned*)&cs;
                    if (gid == 0)
                        *(unsigned*)(pb + wid * 128 + iA) = csu;
                }
            }
        }
        __syncthreads();

        // reduce l partials -> 1/l
        if (tid < 128) {
            float s = 0.f;
            #pragma unroll
            for (int w = 0; w < 16; w++)
                s += __half2float(((__half*)(smem + OFF_PB))[w * 128 + tid]);
            ((float*)(smem + OFF_SL))[tid] = 1.0f / s;
        }
        __syncthreads();

        // fold 1/l_i into V's chunk columns
        {
            const float* sl = (const float*)(smem + OFF_SL);
            for (int idx = tid; idx < 4096; idx += 512) {
                int c = idx >> 6, hp = idx & 63;
                int i0 = hp << 1;
                __half2* vp = (__half2*)(smem + OFF_V + c * 528 + chunk * 256 + hp * 4);
                *vp = __hmul2(*vp, __floats2half2_rn(sl[i0], sl[i0 + 1]));
            }
        }
        __syncthreads();

        // O-GEMM K-chunk: acc += V'[c][k] * P^T[j][k]
        {
            unsigned aaddr = abase + (unsigned)chunk * 256u;
            #pragma unroll
            for (int kk = 0; kk < 8; kk++) {
                unsigned a0, a1, a2, a3;
                ldsm_x4(aaddr + (unsigned)kk * 32u, a0, a1, a2, a3);
                #pragma unroll
                for (int g = 0; g < 4; g++) {
                    unsigned b0, b1, b2, b3;
                    ldsm_x4(bbase + (unsigned)g * (16u * 272u) + (unsigned)kk * 32u,
                            b0, b1, b2, b3);
                    mma16816(acc[2 * g],     a0, a1, a2, a3, b0, b1);
                    mma16816(acc[2 * g + 1], a0, a1, a2, a3, b2, b3);
                }
            }
        }
        __syncthreads();
    }

    // ---- stage O fp16 in smem (reuse PT, stride 264 halfs), coalesced store ----
    {
        __half* so = (__half*)(smem + OFF_PT);
        int crow = mc * 16 + gid;
        int jb2  = jc * 64 + tid2 * 2;
        #pragma unroll
        for (int nt = 0; nt < 8; nt++) {
            int j = jb2 + nt * 8;
            *(__half2*)(so + crow * 264 + j)       = __floats2half2_rn(acc[nt][0], acc[nt][1]);
            *(__half2*)(so + (crow + 8) * 264 + j) = __floats2half2_rn(acc[nt][2], acc[nt][3]);
        }
        __syncthreads();
        for (int idx = tid; idx < 2048; idx += 512) {
            int c = idx >> 5, seg = idx & 31;
            ((uint4*)(o0 + (c << 16)))[seg] = *(uint4*)(so + c * 264 + seg * 8);
        }
    }
}

// ---- K3: out = gamma*(h_out + w_out) + x (fp16 h/w, fp32 out) ----
__global__ void combine_kernel(const float* __restrict__ x,
                               const float* __restrict__ gamma,
                               float* __restrict__ out)
{
    __shared__ __half t[32][33];
    int plane = blockIdx.z;
    const __half* hT = g_hT + ((long)plane << 16);
    const __half* wf = g_w  + ((long)plane << 16);
    const float*  xp = x    + ((long)plane << 16);
    float*        op = out  + ((long)plane << 16);
    int h0 = blockIdx.y << 5, w0 = blockIdx.x << 5;
    int tx = threadIdx.x, ty = threadIdx.y;
    float g = gamma[0];
    #pragma unroll
    for (int yy = 0; yy < 32; yy += 8)
        t[ty + yy][tx] = hT[(w0 + ty + yy) * 256 + h0 + tx];
    __syncthreads();
    #pragma unroll
    for (int yy = 0; yy < 32; yy += 8) {
        int idx = (h0 + ty + yy) * 256 + w0 + tx;
        op[idx] = fmaf(g, __half2float(t[tx][ty + yy]) + __half2float(wf[idx]), xp[idx]);
    }
}

extern "C" void kernel_launch(void* const* d_in, const int* in_sizes, int n_in,
                              void* d_out, int out_size) {
    const float* x     = (const float*)d_in[0];
    const float* Wq    = (const float*)d_in[1];
    const float* bq    = (const float*)d_in[2];
    const float* Wk    = (const float*)d_in[3];
    const float* bk    = (const float*)d_in[4];
    const float* Wv    = (const float*)d_in[5];
    const float* bv    = (const float*)d_in[6];
    const float* gamma = (const float*)d_in[7];
    float* out = (float*)d_out;

    cudaFuncSetAttribute(attn_kernel,
                         cudaFuncAttributeMaxDynamicSharedMemorySize, ATTN_SMEM);

    proj_kernel<<<2048, 256>>>(x, Wq, bq, Wk, bk, Wv, bv);
    transpose_qk<<<dim3(16, 16, 16), dim3(16, 16)>>>();
    transpose_v<<<dim3(4, 4, 512), 256>>>();
    attn_kernel<<<4096, 512, ATTN_SMEM>>>();
    combine_kernel<<<dim3(8, 8, 512), dim3(32, 8)>>>(x, gamma, out);
}